// round 3
// baseline (speedup 1.0000x reference)
#include <cuda_runtime.h>
#include <math.h>
#include <stdint.h>

#define NV 4096
#define NG 2048
#define DD 64
#define KK 128
#define NBLK 4
#define EE 32768

// ---------------- scratch (device globals; no allocation allowed) ----------------
__device__ float g_rbf [NV * NG];        // [NV, NG]
__device__ float g_rbfT[NG * NV];        // [NG, NV]
__device__ float g_adj [NG * NG];        // dense normalized adjacency [dst, src]
__device__ float g_f   [NV * 192];       // [NV, 192] = [x | x_diff | gfeat]
__device__ float g_y   [2 * NV * 64];    // double-buffered diff_x
__device__ float g_cat [NV * 128];       // [gX | gY]
__device__ float g_b2  [2 * NV * 64];    // [b_re ; b_im]
__device__ float g_h1  [NV * 64];
__device__ float g_h2  [NV * 64];
__device__ float g_mx  [NV * 64];        // mass * x
__device__ float g_cs  [KK * 64];        // coef * x_spec
__device__ float g_W   [2 * KK * 64];    // [Wre ; Wim]
__device__ float g_GE  [2 * NV * 128];   // [gradX@evecs ; gradY@evecs]
__device__ float g_eT  [KK * NV];        // evecs^T
__device__ float g_hw  [NG * 64];
__device__ float g_hg  [NG * 64];
__device__ float g_gx2 [NG * 64];
__device__ float g_deg [NG];
__device__ float g_dinv[NG];
// contiguous zero region: [xs (8192) | gx (131072) | agg (131072) | agg2 (131072)]
#define SCR_TOTAL (8192 + 3 * 131072)
__device__ float g_scr [SCR_TOTAL];

// ---------------- tf32 helpers ----------------
__device__ __forceinline__ float tf32r(float x) {
    uint32_t r;
    asm("cvt.rna.tf32.f32 %0, %1;" : "=r"(r) : "f"(x));
    return __uint_as_float(r);
}
__device__ __forceinline__ void mma_tf32(float* c, const uint32_t* a, const uint32_t* b) {
    asm volatile(
        "mma.sync.aligned.m16n8k8.row.col.f32.tf32.tf32.f32 "
        "{%0,%1,%2,%3}, {%4,%5,%6,%7}, {%8,%9}, {%0,%1,%2,%3};"
        : "+f"(c[0]), "+f"(c[1]), "+f"(c[2]), "+f"(c[3])
        : "r"(a[0]), "r"(a[1]), "r"(a[2]), "r"(a[3]), "r"(b[0]), "r"(b[1]));
}

// ---------------- generic N=64 GEMM (tensor-core tf32), BM=64, 64 threads ----------
// C[M,64] = A[M,KB] @ B[KB,64]; z selects A (zA mask) / B (bit0) / C offset.
// gridDim.y > 1 => split-K atomicAdd (caller zero-inits C).
__global__ __launch_bounds__(64) void gemm64(
    const float* __restrict__ A0, const float* __restrict__ A1, int zA, int lda,
    const float* __restrict__ B0, const float* __restrict__ B1, int ldb,
    float* __restrict__ Cbase, int coff1, int coff2, int ldc,
    int KB, int kchunk,
    const float* __restrict__ bias,
    const float* __restrict__ resid, int ldr,
    int act)
{
    __shared__ float As[64][36];   // stride 36 -> conflict-free fragment reads
    __shared__ float Bs[32][72];   // stride 72 -> conflict-free fragment reads

    const int z = blockIdx.z;
    const float* A = (z & zA) ? A1 : A0;
    const float* B = (z & 1) ? B1 : B0;
    float* C = Cbase + (z & 1) * coff1 + (z >> 1) * coff2;

    const int tid    = threadIdx.x;
    const int warp   = tid >> 5;
    const int lane   = tid & 31;
    const int g      = lane >> 2;
    const int tg     = lane & 3;
    const int m0     = blockIdx.x * 64;
    const int warp_m = warp * 32;
    const int kbeg   = blockIdx.y * kchunk;

    float c[2][8][4];
#pragma unroll
    for (int mi = 0; mi < 2; mi++)
#pragma unroll
        for (int ni = 0; ni < 8; ni++)
#pragma unroll
            for (int r = 0; r < 4; r++) c[mi][ni][r] = 0.0f;

    for (int kb = kbeg; kb < kbeg + kchunk; kb += 32) {
        // A tile: 64 rows x 32 k, tf32-rounded at load
#pragma unroll
        for (int i = 0; i < 8; i++) {
            int q  = tid + i * 64;            // 0..511 float4 ids
            int m  = q >> 3;
            int k4 = q & 7;
            float4 v = *(const float4*)(A + (size_t)(m0 + m) * lda + kb + k4 * 4);
            v.x = tf32r(v.x); v.y = tf32r(v.y); v.z = tf32r(v.z); v.w = tf32r(v.w);
            *(float4*)&As[m][k4 * 4] = v;
        }
        // B tile: 32 x 64, tf32-rounded at load
#pragma unroll
        for (int i = 0; i < 8; i++) {
            int q  = tid + i * 64;            // 0..511 float4 ids
            int k  = q >> 4;
            int n4 = q & 15;
            float4 v = *(const float4*)(B + (size_t)(kb + k) * ldb + n4 * 4);
            v.x = tf32r(v.x); v.y = tf32r(v.y); v.z = tf32r(v.z); v.w = tf32r(v.w);
            *(float4*)&Bs[k][n4 * 4] = v;
        }
        __syncthreads();

#pragma unroll
        for (int k8 = 0; k8 < 32; k8 += 8) {
            uint32_t a[2][4];
#pragma unroll
            for (int mi = 0; mi < 2; mi++) {
                int r0 = warp_m + mi * 16 + g;
                a[mi][0] = __float_as_uint(As[r0][k8 + tg]);
                a[mi][1] = __float_as_uint(As[r0 + 8][k8 + tg]);
                a[mi][2] = __float_as_uint(As[r0][k8 + tg + 4]);
                a[mi][3] = __float_as_uint(As[r0 + 8][k8 + tg + 4]);
            }
            uint32_t b[8][2];
#pragma unroll
            for (int ni = 0; ni < 8; ni++) {
                b[ni][0] = __float_as_uint(Bs[k8 + tg][ni * 8 + g]);
                b[ni][1] = __float_as_uint(Bs[k8 + tg + 4][ni * 8 + g]);
            }
#pragma unroll
            for (int mi = 0; mi < 2; mi++)
#pragma unroll
                for (int ni = 0; ni < 8; ni++)
                    mma_tf32(c[mi][ni], a[mi], b[ni]);
        }
        __syncthreads();
    }

    const bool split = (gridDim.y > 1);
#pragma unroll
    for (int mi = 0; mi < 2; mi++) {
#pragma unroll
        for (int rr = 0; rr < 2; rr++) {
            int m = m0 + warp_m + mi * 16 + g + rr * 8;
#pragma unroll
            for (int ni = 0; ni < 8; ni++) {
                int n = ni * 8 + tg * 2;
                float v0 = c[mi][ni][rr * 2 + 0];
                float v1 = c[mi][ni][rr * 2 + 1];
                if (split) {
                    atomicAdd(&C[(size_t)m * ldc + n],     v0);
                    atomicAdd(&C[(size_t)m * ldc + n + 1], v1);
                } else {
                    if (bias)  { v0 += bias[n]; v1 += bias[n + 1]; }
                    if (resid) { v0 += resid[(size_t)m * ldr + n];
                                 v1 += resid[(size_t)m * ldr + n + 1]; }
                    if (act)   { v0 = fmaxf(v0, 0.0f); v1 = fmaxf(v1, 0.0f); }
                    *(float2*)&C[(size_t)m * ldc + n] = make_float2(v0, v1);
                }
            }
        }
    }
}

// ---------------- rbf coupling + transpose (fast math) ----------------
__device__ __forceinline__ float exp_neg_04(float dist) {
    // exp(-dist/2.5) = 2^(dist * -log2(e)/2.5)
    float t  = dist * -0.5770780163555852f;
    float fn = floorf(t);
    float f  = t - fn;
    float p  = 1.5403530e-4f;
    p = fmaf(p, f, 1.33335581e-3f);
    p = fmaf(p, f, 9.61812911e-3f);
    p = fmaf(p, f, 5.55041087e-2f);
    p = fmaf(p, f, 2.40226507e-1f);
    p = fmaf(p, f, 6.93147181e-1f);
    p = fmaf(p, f, 1.0f);
    int n = (int)fn;
    n = n < -126 ? -126 : n;
    return p * __int_as_float((n + 127) << 23);
}

__global__ void rbf_kernel(const float* __restrict__ vert, const float* __restrict__ gp,
                           float* __restrict__ rbf, float* __restrict__ rbfT)
{
    __shared__ float tile[32][33];
    int tx = threadIdx.x, ty = threadIdx.y;
    int g = blockIdx.x * 32 + tx;
    int v = blockIdx.y * 32 + ty;
    float vx = vert[v * 3], vy = vert[v * 3 + 1], vz = vert[v * 3 + 2];
    float gx = gp[g * 3],  gy = gp[g * 3 + 1],  gz = gp[g * 3 + 2];
    float dx = vx - gx, dy = vy - gy, dz = vz - gz;
    float d2 = fmaf(dx, dx, fmaf(dy, dy, dz * dz));
    d2 = fmaxf(d2, 1e-24f);
    float rs;
    asm("rsqrt.approx.f32 %0, %1;" : "=f"(rs) : "f"(d2));
    float r = exp_neg_04(d2 * rs);
    rbf[(size_t)v * NG + g] = r;
    tile[ty][tx] = r;
    __syncthreads();
    int g2 = blockIdx.x * 32 + ty;
    int v2 = blockIdx.y * 32 + tx;
    rbfT[(size_t)g2 * NV + v2] = tile[tx][ty];
}

// ---------------- transpose evecs ----------------
__global__ void transpose_kernel(const float* __restrict__ in, float* __restrict__ out)
{
    __shared__ float t[32][33];
    int x = blockIdx.x * 32 + threadIdx.x;   // k
    int y = blockIdx.y * 32 + threadIdx.y;   // v
    t[threadIdx.y][threadIdx.x] = in[(size_t)y * 128 + x];
    __syncthreads();
    int ox = blockIdx.y * 32 + threadIdx.x;  // v
    int oy = blockIdx.x * 32 + threadIdx.y;  // k
    out[(size_t)oy * NV + ox] = t[threadIdx.x][threadIdx.y];
}

// ---------------- spectral / elementwise ----------------
__global__ void massx_kernel(const float* __restrict__ y, const float* __restrict__ mass,
                             float* __restrict__ f, float* __restrict__ mx)
{
    int gid = blockIdx.x * 256 + threadIdx.x;   // NV*64
    int v = gid >> 6, d = gid & 63;
    float x = y[gid];
    f[v * 192 + d] = x;
    mx[gid] = mass[v] * x;
}

__global__ void cs_kernel(const float* __restrict__ xs, const float* __restrict__ evals,
                          const float* __restrict__ t, float* __restrict__ cs)
{
    int gid = blockIdx.x * 256 + threadIdx.x;   // KK*64
    int k = gid >> 6, d = gid & 63;
    cs[gid] = expf(-evals[k] * fmaxf(t[d], 1e-8f)) * xs[gid];
}

__global__ void wcat_kernel(const float* __restrict__ are, const float* __restrict__ aim,
                            float* __restrict__ W)
{
    int gid = blockIdx.x * 256 + threadIdx.x;   // KK*64
    int k = gid >> 6, d = gid & 63;
    float wre, wim;
    if (k < 64) { wre = are[k * 64 + d];         wim = aim[k * 64 + d]; }
    else        { wre = -aim[(k - 64) * 64 + d]; wim = are[(k - 64) * 64 + d]; }
    W[gid]           = wre;
    W[KK * 64 + gid] = wim;
}

__global__ void gfeat_kernel(const float* __restrict__ cat, const float* __restrict__ b2,
                             float* __restrict__ f)
{
    int gid = blockIdx.x * 256 + threadIdx.x;   // NV*64
    int v = gid >> 6, d = gid & 63;
    float gx = cat[v * 128 + d];
    float gy = cat[v * 128 + 64 + d];
    float bre = b2[gid];
    float bim = b2[NV * 64 + gid];
    f[v * 192 + 128 + d] = tanhf(gx * bre + gy * bim);
}

// ---------------- graph setup ----------------
__global__ void deg_kernel(const int* __restrict__ dst, float* __restrict__ deg)
{
    int e = blockIdx.x * 256 + threadIdx.x;
    atomicAdd(&deg[dst[e]], 1.0f);
}
__global__ void dinv_kernel(const float* __restrict__ deg, float* __restrict__ dinv)
{
    int i = blockIdx.x * 256 + threadIdx.x;
    dinv[i] = rsqrtf(deg[i] + 1.0f);
}
__global__ void adj_edge_kernel(const int* __restrict__ src, const int* __restrict__ dst,
                                const float* __restrict__ dinv, float* __restrict__ adj)
{
    int e = blockIdx.x * 256 + threadIdx.x;
    int s = src[e], t = dst[e];
    atomicAdd(&adj[(size_t)t * NG + s], dinv[s] * dinv[t]);
}
__global__ void adj_diag_kernel(const float* __restrict__ dinv, float* __restrict__ adj)
{
    int i = blockIdx.x * 256 + threadIdx.x;
    float di = dinv[i];
    adj[(size_t)i * NG + i] += di * di;
}
__global__ void finalize_kernel(const float* __restrict__ agg, const float* __restrict__ b,
                                float* __restrict__ out, int relu)
{
    int gid = blockIdx.x * 256 + threadIdx.x;   // NG*64
    int d = gid & 63;
    float v = agg[gid] + b[d];
    out[gid] = relu ? fmaxf(v, 0.0f) : v;
}

// ---------------- head / tail ----------------
__global__ void lin1_kernel(const float* __restrict__ sx, const float* __restrict__ w,
                            const float* __restrict__ b, float* __restrict__ y)
{
    int gid = blockIdx.x * 256 + threadIdx.x;   // NV*64
    int v = gid >> 6, d = gid & 63;
    float acc = b[d];
#pragma unroll
    for (int j = 0; j < 5; j++) acc += sx[v * 5 + j] * w[j * 64 + d];
    y[gid] = acc;
}

__global__ void out_kernel(const float* __restrict__ y, const float* __restrict__ w,
                           const float* __restrict__ b, float* __restrict__ out)
{
    int gid = blockIdx.x * 256 + threadIdx.x;   // NV*8
    int v = gid >> 3, c = gid & 7;
    float acc = b[c];
#pragma unroll 8
    for (int d = 0; d < 64; d++) acc += y[v * 64 + d] * w[d * 8 + c];
    out[gid] = acc;
}

// ---------------- host ----------------
extern "C" void kernel_launch(void* const* d_in, const int* in_sizes, int n_in,
                              void* d_out, int out_size)
{
    static bool inited = false;
    static float *p_rbf, *p_rbfT, *p_adj, *p_f, *p_y, *p_cat, *p_b2, *p_h1, *p_h2,
                 *p_mx, *p_cs, *p_W, *p_GE, *p_eT, *p_hw, *p_hg, *p_gx2,
                 *p_deg, *p_dinv, *p_scr;
    if (!inited) {
        cudaGetSymbolAddress((void**)&p_rbf,  g_rbf);
        cudaGetSymbolAddress((void**)&p_rbfT, g_rbfT);
        cudaGetSymbolAddress((void**)&p_adj,  g_adj);
        cudaGetSymbolAddress((void**)&p_f,    g_f);
        cudaGetSymbolAddress((void**)&p_y,    g_y);
        cudaGetSymbolAddress((void**)&p_cat,  g_cat);
        cudaGetSymbolAddress((void**)&p_b2,   g_b2);
        cudaGetSymbolAddress((void**)&p_h1,   g_h1);
        cudaGetSymbolAddress((void**)&p_h2,   g_h2);
        cudaGetSymbolAddress((void**)&p_mx,   g_mx);
        cudaGetSymbolAddress((void**)&p_cs,   g_cs);
        cudaGetSymbolAddress((void**)&p_W,    g_W);
        cudaGetSymbolAddress((void**)&p_GE,   g_GE);
        cudaGetSymbolAddress((void**)&p_eT,   g_eT);
        cudaGetSymbolAddress((void**)&p_hw,   g_hw);
        cudaGetSymbolAddress((void**)&p_hg,   g_hg);
        cudaGetSymbolAddress((void**)&p_gx2,  g_gx2);
        cudaGetSymbolAddress((void**)&p_deg,  g_deg);
        cudaGetSymbolAddress((void**)&p_dinv, g_dinv);
        cudaGetSymbolAddress((void**)&p_scr,  g_scr);
        inited = true;
    }
    float* p_xs   = p_scr;
    float* p_gx   = p_scr + 8192;
    float* p_agg  = p_scr + 8192 + 131072;
    float* p_agg2 = p_scr + 8192 + 2 * 131072;

    const float* surf_x    = (const float*)d_in[0];
    const float* mass      = (const float*)d_in[1];
    const float* evals     = (const float*)d_in[2];
    const float* evecs     = (const float*)d_in[3];
    const float* gradX     = (const float*)d_in[4];
    const float* gradY     = (const float*)d_in[5];
    const float* vertices  = (const float*)d_in[6];
    const float* graph_pos = (const float*)d_in[8];
    const float* lin1_w    = (const float*)d_in[9];
    const float* lin1_b    = (const float*)d_in[10];
    const float* last_w    = (const float*)d_in[13];
    const float* last_b    = (const float*)d_in[14];
    const float* diff_time = (const float*)d_in[15];
    const float* A_re      = (const float*)d_in[16];
    const float* A_im      = (const float*)d_in[17];
    const float* mlp_w0    = (const float*)d_in[18];
    const float* mlp_b0    = (const float*)d_in[19];
    const float* mlp_w1    = (const float*)d_in[20];
    const float* mlp_b1    = (const float*)d_in[21];
    const float* mlp_w2    = (const float*)d_in[22];
    const float* mlp_b2    = (const float*)d_in[23];
    const float* gcn_w1    = (const float*)d_in[24];
    const float* gcn_b1    = (const float*)d_in[25];
    const float* gcn_w2    = (const float*)d_in[26];
    const float* gcn_b2    = (const float*)d_in[27];
    const int*   eidx      = (const int*)d_in[28];
    const int*   e_src     = eidx;
    const int*   e_dst     = eidx + EE;
    float* out = (float*)d_out;

    // ---- setup ----
    rbf_kernel<<<dim3(NG / 32, NV / 32), dim3(32, 32)>>>(vertices, graph_pos, p_rbf, p_rbfT);

    cudaMemsetAsync(p_deg, 0, NG * sizeof(float));
    deg_kernel<<<EE / 256, 256>>>(e_dst, p_deg);
    dinv_kernel<<<NG / 256, 256>>>(p_deg, p_dinv);
    cudaMemsetAsync(p_adj, 0, (size_t)NG * NG * sizeof(float));
    adj_edge_kernel<<<EE / 256, 256>>>(e_src, e_dst, p_dinv, p_adj);
    adj_diag_kernel<<<NG / 256, 256>>>(p_dinv, p_adj);

    transpose_kernel<<<dim3(KK / 32, NV / 32), dim3(32, 32)>>>(evecs, p_eT);
    lin1_kernel<<<NV * 64 / 256, 256>>>(surf_x, lin1_w, lin1_b, p_y);   // -> y[0]

    // GE = [gradX@evecs ; gradY@evecs]
    gemm64<<<dim3(NV / 64, 1, 4), 64>>>(
        gradX, gradY, /*zA=*/2, NV,
        evecs, evecs + 64, 128,
        p_GE, /*coff1=*/64, /*coff2=*/NV * 128, /*ldc=*/128,
        NV, NV, nullptr, nullptr, 0, 0);

    for (int blk = 0; blk < NBLK; blk++) {
        const float* t   = diff_time + blk * 64;
        const float* are = A_re + blk * 64 * 64;
        const float* aim = A_im + blk * 64 * 64;
        const float* w0  = mlp_w0 + blk * 192 * 64;
        const float* b0  = mlp_b0 + blk * 64;
        const float* w1  = mlp_w1 + blk * 64 * 64;
        const float* b1  = mlp_b1 + blk * 64;
        const float* w2  = mlp_w2 + blk * 64 * 64;
        const float* b2m = mlp_b2 + blk * 64;
        const float* gw1 = gcn_w1 + blk * 64 * 64;
        const float* gb1 = gcn_b1 + blk * 64;
        const float* gw2 = gcn_w2 + blk * 64 * 64;
        const float* gb2 = gcn_b2 + blk * 64;
        float* yA = p_y + (blk & 1) * NV * 64;        // read
        float* yB = p_y + (1 - (blk & 1)) * NV * 64;  // write

        // zero all split-K targets for this block
        cudaMemsetAsync(p_scr, 0, SCR_TOTAL * sizeof(float));
        cudaMemsetAsync(yB, 0, NV * 64 * sizeof(float));

        // x -> f[:,0:64], mx = mass * x
        massx_kernel<<<NV * 64 / 256, 256>>>(yA, mass, p_f, p_mx);

        // xs = evecsT @ mx  (split-K 32)
        gemm64<<<dim3(2, 32, 1), 64>>>(
            p_eT, p_eT, 0, NV, p_mx, p_mx, 64,
            p_xs, 0, 0, 64, NV, NV / 32, nullptr, nullptr, 0, 0);
        cs_kernel<<<KK * 64 / 256, 256>>>(p_xs, evals, t, p_cs);

        // x_diff = evecs @ cs -> f[:,64:128]
        gemm64<<<dim3(NV / 64, 1, 1), 64>>>(
            evecs, evecs, 0, 128, p_cs, p_cs, 64,
            p_f + 64, 0, 0, 192, KK, KK, nullptr, nullptr, 0, 0);

        // gX|gY = GE @ cs
        gemm64<<<dim3(NV / 64, 1, 2), 64>>>(
            p_GE, p_GE + NV * 128, /*zA=*/1, 128, p_cs, p_cs, 64,
            p_cat, 64, 0, 128, KK, KK, nullptr, nullptr, 0, 0);

        // b_re|b_im = cat @ [Wre|Wim]
        wcat_kernel<<<KK * 64 / 256, 256>>>(are, aim, p_W);
        gemm64<<<dim3(NV / 64, 1, 2), 64>>>(
            p_cat, p_cat, 0, 128, p_W, p_W + KK * 64, 64,
            p_b2, NV * 64, 0, 64, KK, KK, nullptr, nullptr, 0, 0);

        gfeat_kernel<<<NV * 64 / 256, 256>>>(p_cat, p_b2, p_f);

        // MLP
        gemm64<<<dim3(NV / 64, 1, 1), 64>>>(
            p_f, p_f, 0, 192, w0, w0, 64, p_h1, 0, 0, 64, 192, 192, b0, nullptr, 0, 1);
        gemm64<<<dim3(NV / 64, 1, 1), 64>>>(
            p_h1, p_h1, 0, 64, w1, w1, 64, p_h2, 0, 0, 64, 64, 64, b1, nullptr, 0, 1);
        gemm64<<<dim3(NV / 64, 1, 1), 64>>>(
            p_h2, p_h2, 0, 64, w2, w2, 64, p_f, 0, 0, 192, 64, 64, b2m, p_f, 192, 0);

        // gx = rbf^T @ diff_x (split-K 8)
        gemm64<<<dim3(NG / 64, 8, 1), 64>>>(
            p_rbfT, p_rbfT, 0, NV, p_f, p_f, 192,
            p_gx, 0, 0, 64, NV, NV / 8, nullptr, nullptr, 0, 0);

        // GCN layer 1: H = gx@W1 ; agg = adj@H ; relu(agg+b)
        gemm64<<<dim3(NG / 64, 1, 1), 64>>>(
            p_gx, p_gx, 0, 64, gw1, gw1, 64, p_hw, 0, 0, 64, 64, 64, nullptr, nullptr, 0, 0);
        gemm64<<<dim3(NG / 64, 4, 1), 64>>>(
            p_adj, p_adj, 0, NG, p_hw, p_hw, 64,
            p_agg, 0, 0, 64, NG, NG / 4, nullptr, nullptr, 0, 0);
        finalize_kernel<<<NG * 64 / 256, 256>>>(p_agg, gb1, p_hg, 1);

        // GCN layer 2
        gemm64<<<dim3(NG / 64, 1, 1), 64>>>(
            p_hg, p_hg, 0, 64, gw2, gw2, 64, p_hw, 0, 0, 64, 64, 64, nullptr, nullptr, 0, 0);
        gemm64<<<dim3(NG / 64, 4, 1), 64>>>(
            p_adj, p_adj, 0, NG, p_hw, p_hw, 64,
            p_agg2, 0, 0, 64, NG, NG / 4, nullptr, nullptr, 0, 0);
        finalize_kernel<<<NG * 64 / 256, 256>>>(p_agg2, gb2, p_gx2, 0);

        // diff_x = rbf @ gx2 -> yB (split-K 4)
        gemm64<<<dim3(NV / 64, 4, 1), 64>>>(
            p_rbf, p_rbf, 0, NG, p_gx2, p_gx2, 64,
            yB, 0, 0, 64, NG, NG / 4, nullptr, nullptr, 0, 0);
    }

    // final: out = y[0] @ last_w + last_b   (after 4 blocks result is in buffer 0)
    out_kernel<<<(NV * 8) / 256, 256>>>(p_y, last_w, last_b, out);
}

// round 4
// speedup vs baseline: 1.3712x; 1.3712x over previous
#include <cuda_runtime.h>
#include <math.h>
#include <stdint.h>

#define NV 4096
#define NG 2048
#define DD 64
#define KK 128
#define NBLK 4
#define EE 32768

// ---------------- scratch (device globals; no allocation allowed) ----------------
__device__ float g_rbf [NV * NG];        // [NV, NG]
__device__ float g_rbfT[NG * NV];        // [NG, NV]
__device__ float g_f   [NV * 192];       // [NV, 192] = [x | x_diff | gfeat]
__device__ float g_y   [2 * NV * 64];    // double-buffered diff_x
__device__ float g_cat [NV * 128];       // [gX | gY]
__device__ float g_b2  [2 * NV * 64];    // [b_re ; b_im]
__device__ float g_h1  [NV * 64];
__device__ float g_h2  [NV * 64];
__device__ float g_mx  [NV * 64];        // mass * x
__device__ float g_xs  [KK * 64];
__device__ float g_cs  [KK * 64];
__device__ float g_W   [2 * KK * 64];    // [Wre ; Wim]
__device__ float g_GE  [2 * NV * 128];   // [gradX@evecs ; gradY@evecs]
__device__ float g_eT  [KK * NV];        // evecs^T
__device__ float g_gx  [NG * 64];
__device__ float g_hw  [NG * 64];
__device__ float g_agg [NG * 64];
__device__ float g_hg  [NG * 64];
__device__ float g_gx2 [NG * 64];
__device__ float g_deg [NG];
__device__ float g_dinv[NG];

// ---------------- tf32 helpers ----------------
__device__ __forceinline__ float tf32r(float x) {
    uint32_t r;
    asm("cvt.rna.tf32.f32 %0, %1;" : "=r"(r) : "f"(x));
    return __uint_as_float(r);
}
__device__ __forceinline__ void mma_tf32(float* c, const uint32_t* a, const uint32_t* b) {
    asm volatile(
        "mma.sync.aligned.m16n8k8.row.col.f32.tf32.tf32.f32 "
        "{%0,%1,%2,%3}, {%4,%5,%6,%7}, {%8,%9}, {%0,%1,%2,%3};"
        : "+f"(c[0]), "+f"(c[1]), "+f"(c[2]), "+f"(c[3])
        : "r"(a[0]), "r"(a[1]), "r"(a[2]), "r"(a[3]), "r"(b[0]), "r"(b[1]));
}

// ---------------- generic N=64 GEMM (tf32 MMA), BM=128, 128 threads ----------------
// C[M,64] = A[M,KB] @ B[KB,64]; z selects A (zA mask) / B (bit0) / C offset.
// gridDim.y > 1 => split-K atomicAdd (caller zero-inits C).
__global__ __launch_bounds__(128) void gemm64(
    const float* __restrict__ A0, const float* __restrict__ A1, int zA, int lda,
    const float* __restrict__ B0, const float* __restrict__ B1, int ldb,
    float* __restrict__ Cbase, int coff1, int coff2, int ldc,
    int KB, int kchunk,
    const float* __restrict__ bias,
    const float* __restrict__ resid, int ldr,
    int act)
{
    __shared__ float As[128][36];   // stride 36 -> conflict-free fragment reads
    __shared__ float Bs[32][72];    // stride 72 -> conflict-free fragment reads

    const int z = blockIdx.z;
    const float* A = (z & zA) ? A1 : A0;
    const float* B = (z & 1) ? B1 : B0;
    float* C = Cbase + (z & 1) * coff1 + (z >> 1) * coff2;

    const int tid    = threadIdx.x;
    const int warp   = tid >> 5;
    const int lane   = tid & 31;
    const int g      = lane >> 2;
    const int tg     = lane & 3;
    const int m0     = blockIdx.x * 128;
    const int warp_m = warp * 32;
    const int kbeg   = blockIdx.y * kchunk;

    float c[2][8][4];
#pragma unroll
    for (int mi = 0; mi < 2; mi++)
#pragma unroll
        for (int ni = 0; ni < 8; ni++)
#pragma unroll
            for (int r = 0; r < 4; r++) c[mi][ni][r] = 0.0f;

    for (int kb = kbeg; kb < kbeg + kchunk; kb += 32) {
        // A tile: 128 rows x 32 k, tf32-rounded at load
#pragma unroll
        for (int i = 0; i < 8; i++) {
            int q  = tid + i * 128;           // 0..1023 float4 ids
            int m  = q >> 3;
            int k4 = q & 7;
            float4 v = *(const float4*)(A + (size_t)(m0 + m) * lda + kb + k4 * 4);
            v.x = tf32r(v.x); v.y = tf32r(v.y); v.z = tf32r(v.z); v.w = tf32r(v.w);
            *(float4*)&As[m][k4 * 4] = v;
        }
        // B tile: 32 x 64, tf32-rounded at load
#pragma unroll
        for (int i = 0; i < 4; i++) {
            int q  = tid + i * 128;           // 0..511 float4 ids
            int k  = q >> 4;
            int n4 = q & 15;
            float4 v = *(const float4*)(B + (size_t)(kb + k) * ldb + n4 * 4);
            v.x = tf32r(v.x); v.y = tf32r(v.y); v.z = tf32r(v.z); v.w = tf32r(v.w);
            *(float4*)&Bs[k][n4 * 4] = v;
        }
        __syncthreads();

#pragma unroll
        for (int k8 = 0; k8 < 32; k8 += 8) {
            uint32_t a[2][4];
#pragma unroll
            for (int mi = 0; mi < 2; mi++) {
                int r0 = warp_m + mi * 16 + g;
                a[mi][0] = __float_as_uint(As[r0][k8 + tg]);
                a[mi][1] = __float_as_uint(As[r0 + 8][k8 + tg]);
                a[mi][2] = __float_as_uint(As[r0][k8 + tg + 4]);
                a[mi][3] = __float_as_uint(As[r0 + 8][k8 + tg + 4]);
            }
            uint32_t b[8][2];
#pragma unroll
            for (int ni = 0; ni < 8; ni++) {
                b[ni][0] = __float_as_uint(Bs[k8 + tg][ni * 8 + g]);
                b[ni][1] = __float_as_uint(Bs[k8 + tg + 4][ni * 8 + g]);
            }
#pragma unroll
            for (int mi = 0; mi < 2; mi++)
#pragma unroll
                for (int ni = 0; ni < 8; ni++)
                    mma_tf32(c[mi][ni], a[mi], b[ni]);
        }
        __syncthreads();
    }

    const bool split = (gridDim.y > 1);
#pragma unroll
    for (int mi = 0; mi < 2; mi++) {
#pragma unroll
        for (int rr = 0; rr < 2; rr++) {
            int m = m0 + warp_m + mi * 16 + g + rr * 8;
#pragma unroll
            for (int ni = 0; ni < 8; ni++) {
                int n = ni * 8 + tg * 2;
                float v0 = c[mi][ni][rr * 2 + 0];
                float v1 = c[mi][ni][rr * 2 + 1];
                if (split) {
                    atomicAdd(&C[(size_t)m * ldc + n],     v0);
                    atomicAdd(&C[(size_t)m * ldc + n + 1], v1);
                } else {
                    if (bias)  { v0 += bias[n]; v1 += bias[n + 1]; }
                    if (resid) { v0 += resid[(size_t)m * ldr + n];
                                 v1 += resid[(size_t)m * ldr + n + 1]; }
                    if (act)   { v0 = fmaxf(v0, 0.0f); v1 = fmaxf(v1, 0.0f); }
                    *(float2*)&C[(size_t)m * ldc + n] = make_float2(v0, v1);
                }
            }
        }
    }
}

// ---------------- rbf coupling + transpose (fast math) ----------------
__device__ __forceinline__ float exp_neg_04(float dist) {
    // exp(-dist/2.5) = 2^(dist * -log2(e)/2.5)
    float t  = dist * -0.5770780163555852f;
    float fn = floorf(t);
    float f  = t - fn;
    float p  = 1.5403530e-4f;
    p = fmaf(p, f, 1.33335581e-3f);
    p = fmaf(p, f, 9.61812911e-3f);
    p = fmaf(p, f, 5.55041087e-2f);
    p = fmaf(p, f, 2.40226507e-1f);
    p = fmaf(p, f, 6.93147181e-1f);
    p = fmaf(p, f, 1.0f);
    int n = (int)fn;
    n = n < -126 ? -126 : n;
    return p * __int_as_float((n + 127) << 23);
}

__global__ void rbf_kernel(const float* __restrict__ vert, const float* __restrict__ gp,
                           float* __restrict__ rbf, float* __restrict__ rbfT)
{
    __shared__ float tile[32][33];
    int tx = threadIdx.x, ty = threadIdx.y;
    int g = blockIdx.x * 32 + tx;
    int v = blockIdx.y * 32 + ty;
    float vx = vert[v * 3], vy = vert[v * 3 + 1], vz = vert[v * 3 + 2];
    float gx = gp[g * 3],  gy = gp[g * 3 + 1],  gz = gp[g * 3 + 2];
    float dx = vx - gx, dy = vy - gy, dz = vz - gz;
    float d2 = fmaf(dx, dx, fmaf(dy, dy, dz * dz));
    d2 = fmaxf(d2, 1e-24f);
    float rs;
    asm("rsqrt.approx.f32 %0, %1;" : "=f"(rs) : "f"(d2));
    float r = exp_neg_04(d2 * rs);
    rbf[(size_t)v * NG + g] = r;
    tile[ty][tx] = r;
    __syncthreads();
    int g2 = blockIdx.x * 32 + ty;
    int v2 = blockIdx.y * 32 + tx;
    rbfT[(size_t)g2 * NV + v2] = tile[tx][ty];
}

// ---------------- transpose evecs ----------------
__global__ void transpose_kernel(const float* __restrict__ in, float* __restrict__ out)
{
    __shared__ float t[32][33];
    int x = blockIdx.x * 32 + threadIdx.x;   // k
    int y = blockIdx.y * 32 + threadIdx.y;   // v
    t[threadIdx.y][threadIdx.x] = in[(size_t)y * 128 + x];
    __syncthreads();
    int ox = blockIdx.y * 32 + threadIdx.x;  // v
    int oy = blockIdx.x * 32 + threadIdx.y;  // k
    out[(size_t)oy * NV + ox] = t[threadIdx.x][threadIdx.y];
}

// ---------------- spectral / elementwise ----------------
__global__ void massx_kernel(const float* __restrict__ y, const float* __restrict__ mass,
                             float* __restrict__ f, float* __restrict__ mx)
{
    int gid = blockIdx.x * 256 + threadIdx.x;   // NV*64
    int v = gid >> 6, d = gid & 63;
    float x = y[gid];
    f[v * 192 + d] = x;
    mx[gid] = mass[v] * x;
}

__global__ void cs_kernel(const float* __restrict__ xs, const float* __restrict__ evals,
                          const float* __restrict__ t, float* __restrict__ cs)
{
    int gid = blockIdx.x * 256 + threadIdx.x;   // KK*64
    int k = gid >> 6, d = gid & 63;
    cs[gid] = expf(-evals[k] * fmaxf(t[d], 1e-8f)) * xs[gid];
}

__global__ void wcat_kernel(const float* __restrict__ are, const float* __restrict__ aim,
                            float* __restrict__ W)
{
    int gid = blockIdx.x * 256 + threadIdx.x;   // KK*64
    int k = gid >> 6, d = gid & 63;
    float wre, wim;
    if (k < 64) { wre = are[k * 64 + d];         wim = aim[k * 64 + d]; }
    else        { wre = -aim[(k - 64) * 64 + d]; wim = are[(k - 64) * 64 + d]; }
    W[gid]           = wre;
    W[KK * 64 + gid] = wim;
}

__global__ void gfeat_kernel(const float* __restrict__ cat, const float* __restrict__ b2,
                             float* __restrict__ f)
{
    int gid = blockIdx.x * 256 + threadIdx.x;   // NV*64
    int v = gid >> 6, d = gid & 63;
    float gx = cat[v * 128 + d];
    float gy = cat[v * 128 + 64 + d];
    float bre = b2[gid];
    float bim = b2[NV * 64 + gid];
    f[v * 192 + 128 + d] = tanhf(gx * bre + gy * bim);
}

// ---------------- GCN helpers (sparse path) ----------------
__global__ void deg_kernel(const int* __restrict__ dst, float* __restrict__ deg)
{
    int e = blockIdx.x * 256 + threadIdx.x;
    atomicAdd(&deg[dst[e]], 1.0f);
}
__global__ void dinv_kernel(const float* __restrict__ deg, float* __restrict__ dinv)
{
    int i = blockIdx.x * 256 + threadIdx.x;
    dinv[i] = rsqrtf(deg[i] + 1.0f);
}
__global__ void selfloop_kernel(const float* __restrict__ hw, const float* __restrict__ dinv,
                                float* __restrict__ agg)
{
    int gid = blockIdx.x * 256 + threadIdx.x;   // NG*64
    int i = gid >> 6;
    float di = dinv[i];
    agg[gid] = hw[gid] * di * di;
}
__global__ void edge_kernel(const int* __restrict__ src, const int* __restrict__ dst,
                            const float* __restrict__ hw, const float* __restrict__ dinv,
                            float* __restrict__ agg)
{
    int e = blockIdx.x * 4 + (threadIdx.x >> 6);
    int d = threadIdx.x & 63;
    int s = src[e], t = dst[e];
    atomicAdd(&agg[t * 64 + d], hw[s * 64 + d] * dinv[s] * dinv[t]);
}
__global__ void finalize_kernel(const float* __restrict__ agg, const float* __restrict__ b,
                                float* __restrict__ out, int relu)
{
    int gid = blockIdx.x * 256 + threadIdx.x;   // NG*64
    int d = gid & 63;
    float v = agg[gid] + b[d];
    out[gid] = relu ? fmaxf(v, 0.0f) : v;
}

// ---------------- head / tail ----------------
__global__ void lin1_kernel(const float* __restrict__ sx, const float* __restrict__ w,
                            const float* __restrict__ b, float* __restrict__ y)
{
    int gid = blockIdx.x * 256 + threadIdx.x;   // NV*64
    int v = gid >> 6, d = gid & 63;
    float acc = b[d];
#pragma unroll
    for (int j = 0; j < 5; j++) acc += sx[v * 5 + j] * w[j * 64 + d];
    y[gid] = acc;
}

__global__ void out_kernel(const float* __restrict__ y, const float* __restrict__ w,
                           const float* __restrict__ b, float* __restrict__ out)
{
    int gid = blockIdx.x * 256 + threadIdx.x;   // NV*8
    int v = gid >> 3, c = gid & 7;
    float acc = b[c];
#pragma unroll 8
    for (int d = 0; d < 64; d++) acc += y[v * 64 + d] * w[d * 8 + c];
    out[gid] = acc;
}

// ---------------- host ----------------
extern "C" void kernel_launch(void* const* d_in, const int* in_sizes, int n_in,
                              void* d_out, int out_size)
{
    static bool inited = false;
    static float *p_rbf, *p_rbfT, *p_f, *p_y, *p_cat, *p_b2, *p_h1, *p_h2, *p_mx,
                 *p_xs, *p_cs, *p_W, *p_GE, *p_eT, *p_gx, *p_hw, *p_agg, *p_hg,
                 *p_gx2, *p_deg, *p_dinv;
    if (!inited) {
        cudaGetSymbolAddress((void**)&p_rbf,  g_rbf);
        cudaGetSymbolAddress((void**)&p_rbfT, g_rbfT);
        cudaGetSymbolAddress((void**)&p_f,    g_f);
        cudaGetSymbolAddress((void**)&p_y,    g_y);
        cudaGetSymbolAddress((void**)&p_cat,  g_cat);
        cudaGetSymbolAddress((void**)&p_b2,   g_b2);
        cudaGetSymbolAddress((void**)&p_h1,   g_h1);
        cudaGetSymbolAddress((void**)&p_h2,   g_h2);
        cudaGetSymbolAddress((void**)&p_mx,   g_mx);
        cudaGetSymbolAddress((void**)&p_xs,   g_xs);
        cudaGetSymbolAddress((void**)&p_cs,   g_cs);
        cudaGetSymbolAddress((void**)&p_W,    g_W);
        cudaGetSymbolAddress((void**)&p_GE,   g_GE);
        cudaGetSymbolAddress((void**)&p_eT,   g_eT);
        cudaGetSymbolAddress((void**)&p_gx,   g_gx);
        cudaGetSymbolAddress((void**)&p_hw,   g_hw);
        cudaGetSymbolAddress((void**)&p_agg,  g_agg);
        cudaGetSymbolAddress((void**)&p_hg,   g_hg);
        cudaGetSymbolAddress((void**)&p_gx2,  g_gx2);
        cudaGetSymbolAddress((void**)&p_deg,  g_deg);
        cudaGetSymbolAddress((void**)&p_dinv, g_dinv);
        inited = true;
    }

    const float* surf_x    = (const float*)d_in[0];
    const float* mass      = (const float*)d_in[1];
    const float* evals     = (const float*)d_in[2];
    const float* evecs     = (const float*)d_in[3];
    const float* gradX     = (const float*)d_in[4];
    const float* gradY     = (const float*)d_in[5];
    const float* vertices  = (const float*)d_in[6];
    const float* graph_pos = (const float*)d_in[8];
    const float* lin1_w    = (const float*)d_in[9];
    const float* lin1_b    = (const float*)d_in[10];
    const float* last_w    = (const float*)d_in[13];
    const float* last_b    = (const float*)d_in[14];
    const float* diff_time = (const float*)d_in[15];
    const float* A_re      = (const float*)d_in[16];
    const float* A_im      = (const float*)d_in[17];
    const float* mlp_w0    = (const float*)d_in[18];
    const float* mlp_b0    = (const float*)d_in[19];
    const float* mlp_w1    = (const float*)d_in[20];
    const float* mlp_b1    = (const float*)d_in[21];
    const float* mlp_w2    = (const float*)d_in[22];
    const float* mlp_b2    = (const float*)d_in[23];
    const float* gcn_w1    = (const float*)d_in[24];
    const float* gcn_b1    = (const float*)d_in[25];
    const float* gcn_w2    = (const float*)d_in[26];
    const float* gcn_b2    = (const float*)d_in[27];
    const int*   eidx      = (const int*)d_in[28];
    const int*   e_src     = eidx;
    const int*   e_dst     = eidx + EE;
    float* out = (float*)d_out;

    // ---- setup ----
    rbf_kernel<<<dim3(NG / 32, NV / 32), dim3(32, 32)>>>(vertices, graph_pos, p_rbf, p_rbfT);

    cudaMemsetAsync(p_deg, 0, NG * sizeof(float));
    deg_kernel<<<EE / 256, 256>>>(e_dst, p_deg);
    dinv_kernel<<<NG / 256, 256>>>(p_deg, p_dinv);

    transpose_kernel<<<dim3(KK / 32, NV / 32), dim3(32, 32)>>>(evecs, p_eT);
    lin1_kernel<<<NV * 64 / 256, 256>>>(surf_x, lin1_w, lin1_b, p_y);   // -> y[0]

    // GE = [gradX@evecs ; gradY@evecs]
    gemm64<<<dim3(NV / 128, 1, 4), 128>>>(
        gradX, gradY, /*zA=*/2, NV,
        evecs, evecs + 64, 128,
        p_GE, /*coff1=*/64, /*coff2=*/NV * 128, /*ldc=*/128,
        NV, NV, nullptr, nullptr, 0, 0);

    for (int blk = 0; blk < NBLK; blk++) {
        const float* t   = diff_time + blk * 64;
        const float* are = A_re + blk * 64 * 64;
        const float* aim = A_im + blk * 64 * 64;
        const float* w0  = mlp_w0 + blk * 192 * 64;
        const float* b0  = mlp_b0 + blk * 64;
        const float* w1  = mlp_w1 + blk * 64 * 64;
        const float* b1  = mlp_b1 + blk * 64;
        const float* w2  = mlp_w2 + blk * 64 * 64;
        const float* b2m = mlp_b2 + blk * 64;
        const float* gw1 = gcn_w1 + blk * 64 * 64;
        const float* gb1 = gcn_b1 + blk * 64;
        const float* gw2 = gcn_w2 + blk * 64 * 64;
        const float* gb2 = gcn_b2 + blk * 64;
        float* yA = p_y + (blk & 1) * NV * 64;        // read
        float* yB = p_y + (1 - (blk & 1)) * NV * 64;  // write

        // x -> f[:,0:64], mx = mass * x
        massx_kernel<<<NV * 64 / 256, 256>>>(yA, mass, p_f, p_mx);

        // xs = evecsT @ mx  (split-K 8)
        cudaMemsetAsync(p_xs, 0, KK * 64 * sizeof(float));
        gemm64<<<dim3(1, 8, 1), 128>>>(
            p_eT, p_eT, 0, NV, p_mx, p_mx, 64,
            p_xs, 0, 0, 64, NV, NV / 8, nullptr, nullptr, 0, 0);
        cs_kernel<<<KK * 64 / 256, 256>>>(p_xs, evals, t, p_cs);

        // x_diff = evecs @ cs -> f[:,64:128]
        gemm64<<<dim3(NV / 128, 1, 1), 128>>>(
            evecs, evecs, 0, 128, p_cs, p_cs, 64,
            p_f + 64, 0, 0, 192, KK, KK, nullptr, nullptr, 0, 0);

        // gX|gY = GE @ cs
        gemm64<<<dim3(NV / 128, 1, 2), 128>>>(
            p_GE, p_GE + NV * 128, /*zA=*/1, 128, p_cs, p_cs, 64,
            p_cat, 64, 0, 128, KK, KK, nullptr, nullptr, 0, 0);

        // b_re|b_im = cat @ [Wre|Wim]
        wcat_kernel<<<KK * 64 / 256, 256>>>(are, aim, p_W);
        gemm64<<<dim3(NV / 128, 1, 2), 128>>>(
            p_cat, p_cat, 0, 128, p_W, p_W + KK * 64, 64,
            p_b2, NV * 64, 0, 64, KK, KK, nullptr, nullptr, 0, 0);

        gfeat_kernel<<<NV * 64 / 256, 256>>>(p_cat, p_b2, p_f);

        // MLP
        gemm64<<<dim3(NV / 128, 1, 1), 128>>>(
            p_f, p_f, 0, 192, w0, w0, 64, p_h1, 0, 0, 64, 192, 192, b0, nullptr, 0, 1);
        gemm64<<<dim3(NV / 128, 1, 1), 128>>>(
            p_h1, p_h1, 0, 64, w1, w1, 64, p_h2, 0, 0, 64, 64, 64, b1, nullptr, 0, 1);
        gemm64<<<dim3(NV / 128, 1, 1), 128>>>(
            p_h2, p_h2, 0, 64, w2, w2, 64, p_f, 0, 0, 192, 64, 64, b2m, p_f, 192, 0);

        // gx = rbf^T @ diff_x (split-K 8)
        cudaMemsetAsync(p_gx, 0, NG * 64 * sizeof(float));
        gemm64<<<dim3(NG / 128, 8, 1), 128>>>(
            p_rbfT, p_rbfT, 0, NV, p_f, p_f, 192,
            p_gx, 0, 0, 64, NV, NV / 8, nullptr, nullptr, 0, 0);

        // GCN layer 1 (relu)
        gemm64<<<dim3(NG / 128, 1, 1), 128>>>(
            p_gx, p_gx, 0, 64, gw1, gw1, 64, p_hw, 0, 0, 64, 64, 64, nullptr, nullptr, 0, 0);
        selfloop_kernel<<<NG * 64 / 256, 256>>>(p_hw, p_dinv, p_agg);
        edge_kernel<<<EE / 4, 256>>>(e_src, e_dst, p_hw, p_dinv, p_agg);
        finalize_kernel<<<NG * 64 / 256, 256>>>(p_agg, gb1, p_hg, 1);

        // GCN layer 2 (no relu)
        gemm64<<<dim3(NG / 128, 1, 1), 128>>>(
            p_hg, p_hg, 0, 64, gw2, gw2, 64, p_hw, 0, 0, 64, 64, 64, nullptr, nullptr, 0, 0);
        selfloop_kernel<<<NG * 64 / 256, 256>>>(p_hw, p_dinv, p_agg);
        edge_kernel<<<EE / 4, 256>>>(e_src, e_dst, p_hw, p_dinv, p_agg);
        finalize_kernel<<<NG * 64 / 256, 256>>>(p_agg, gb2, p_gx2, 0);

        // diff_x = rbf @ gx2 -> yB (split-K 4)
        cudaMemsetAsync(yB, 0, NV * 64 * sizeof(float));
        gemm64<<<dim3(NV / 128, 4, 1), 128>>>(
            p_rbf, p_rbf, 0, NG, p_gx2, p_gx2, 64,
            yB, 0, 0, 64, NG, NG / 4, nullptr, nullptr, 0, 0);
    }

    // final: out = y[0] @ last_w + last_b   (after 4 blocks result is in buffer 0)
    out_kernel<<<(NV * 8) / 256, 256>>>(p_y, last_w, last_b, out);
}

// round 5
// speedup vs baseline: 1.8707x; 1.3642x over previous
#include <cuda_runtime.h>
#include <math.h>
#include <stdint.h>

#define NV 4096
#define NG 2048
#define DD 64
#define KK 128
#define NBLK 4
#define EE 32768

// ---------------- scratch (device globals; no allocation allowed) ----------------
__device__ float g_rbf [NV * NG];        // [NV, NG]
__device__ float g_rbfT[NG * NV];        // [NG, NV]
__device__ float g_f   [NV * 192];       // [NV, 192] = [x | x_diff | gfeat]
__device__ float g_y   [2 * NV * 64];    // double-buffered diff_x
__device__ float g_cat [NV * 128];       // [gX | gY]
__device__ float g_b2  [2 * NV * 64];    // [b_re ; b_im]
__device__ float g_h1  [NV * 64];
__device__ float g_h2  [NV * 64];
__device__ float g_mx  [NV * 64];        // mass * x
__device__ float g_xs  [KK * 64];
__device__ float g_cs  [KK * 64];
__device__ float g_W   [2 * KK * 64];    // [Wre ; Wim]
__device__ float g_GE  [2 * NV * 128];   // [gradX@evecs ; gradY@evecs]
__device__ float g_eT  [KK * NV];        // evecs^T
__device__ float g_gx  [NG * 64];
__device__ float g_hw  [NG * 64];
__device__ float g_agg [NG * 64];
__device__ float g_hg  [NG * 64];
__device__ float g_gx2 [NG * 64];
__device__ float g_deg [NG];
__device__ float g_dinv[NG];

// ---------------- tf32 helpers ----------------
__device__ __forceinline__ float tf32r(float x) {
    uint32_t r;
    asm("cvt.rna.tf32.f32 %0, %1;" : "=r"(r) : "f"(x));
    return __uint_as_float(r);
}
__device__ __forceinline__ void mma_tf32(float* c, const uint32_t* a, const uint32_t* b) {
    asm volatile(
        "mma.sync.aligned.m16n8k8.row.col.f32.tf32.tf32.f32 "
        "{%0,%1,%2,%3}, {%4,%5,%6,%7}, {%8,%9}, {%0,%1,%2,%3};"
        : "+f"(c[0]), "+f"(c[1]), "+f"(c[2]), "+f"(c[3])
        : "r"(a[0]), "r"(a[1]), "r"(a[2]), "r"(a[3]), "r"(b[0]), "r"(b[1]));
}

// ---------------- generic N=64 GEMM (tf32 MMA), BM=128, 128 threads -----------
// Register-prefetch double-buffered pipeline: one __syncthreads per k-tile;
// GMEM loads for tile t+1 issue right after the barrier and overlap compute(t).
// C[M,64] = A[M,KB] @ B[KB,64]; z selects A (zA mask) / B (bit0) / C offset.
// gridDim.y > 1 => split-K atomicAdd (caller zero-inits C, no epilogue extras).
// dvec/C2: optional second output C2[m*64+n] = v * dvec[m]^2 (GCN self-loop).
__global__ __launch_bounds__(128) void gemm64(
    const float* __restrict__ A0, const float* __restrict__ A1, int zA, int lda,
    const float* __restrict__ B0, const float* __restrict__ B1, int ldb,
    float* __restrict__ Cbase, int coff1, int coff2, int ldc,
    int KB, int kchunk,
    const float* __restrict__ bias,
    const float* __restrict__ resid, int ldr,
    int act,
    const float* __restrict__ dvec, float* __restrict__ C2)
{
    __shared__ float As[2][128][36];   // stride 36 -> conflict-free fragment reads
    __shared__ float Bs[2][32][72];    // stride 72 -> conflict-free fragment reads

    const int z = blockIdx.z;
    const float* A = (z & zA) ? A1 : A0;
    const float* B = (z & 1) ? B1 : B0;
    float* C = Cbase + (z & 1) * coff1 + (z >> 1) * coff2;

    const int tid    = threadIdx.x;
    const int warp   = tid >> 5;
    const int lane   = tid & 31;
    const int g      = lane >> 2;
    const int tg     = lane & 3;
    const int m0     = blockIdx.x * 128;
    const int warp_m = warp * 32;
    const int kbeg   = blockIdx.y * kchunk;
    const int ntile  = kchunk >> 5;

    // per-thread load coordinates
    const int am = tid >> 3;           // base A row (plus i*16)
    const int ak = (tid & 7) * 4;      // A k offset within tile
    const int bk = tid >> 4;           // base B k (plus i*8)
    const int bn = (tid & 15) * 4;     // B n offset

    float4 rA[8], rB[4];
    float c[2][8][4];
#pragma unroll
    for (int mi = 0; mi < 2; mi++)
#pragma unroll
        for (int ni = 0; ni < 8; ni++)
#pragma unroll
            for (int r = 0; r < 4; r++) c[mi][ni][r] = 0.0f;

    // prologue: load tile 0 into registers
    {
        const float* ap = A + (size_t)(m0 + am) * lda + kbeg + ak;
        const float* bp = B + (size_t)bk * ldb + kbeg * ldb + bn;
#pragma unroll
        for (int i = 0; i < 8; i++) rA[i] = *(const float4*)(ap + (size_t)(i * 16) * lda);
#pragma unroll
        for (int i = 0; i < 4; i++) rB[i] = *(const float4*)(bp + (size_t)(i * 8) * ldb);
    }

    int buf = 0;
    for (int it = 0; it < ntile; it++) {
        // STS (with tf32 rounding) into current buffer
#pragma unroll
        for (int i = 0; i < 8; i++) {
            float4 v = rA[i];
            v.x = tf32r(v.x); v.y = tf32r(v.y); v.z = tf32r(v.z); v.w = tf32r(v.w);
            *(float4*)&As[buf][am + i * 16][ak] = v;
        }
#pragma unroll
        for (int i = 0; i < 4; i++) {
            float4 v = rB[i];
            v.x = tf32r(v.x); v.y = tf32r(v.y); v.z = tf32r(v.z); v.w = tf32r(v.w);
            *(float4*)&Bs[buf][bk + i * 8][bn] = v;
        }
        __syncthreads();

        // prefetch next tile into registers (overlaps with compute below)
        if (it + 1 < ntile) {
            int kb = kbeg + (it + 1) * 32;
            const float* ap = A + (size_t)(m0 + am) * lda + kb + ak;
            const float* bp = B + (size_t)(kb + bk) * ldb + bn;
#pragma unroll
            for (int i = 0; i < 8; i++) rA[i] = *(const float4*)(ap + (size_t)(i * 16) * lda);
#pragma unroll
            for (int i = 0; i < 4; i++) rB[i] = *(const float4*)(bp + (size_t)(i * 8) * ldb);
        }

        // compute from smem buffer
#pragma unroll
        for (int k8 = 0; k8 < 32; k8 += 8) {
            uint32_t a[2][4];
#pragma unroll
            for (int mi = 0; mi < 2; mi++) {
                int r0 = warp_m + mi * 16 + g;
                a[mi][0] = __float_as_uint(As[buf][r0][k8 + tg]);
                a[mi][1] = __float_as_uint(As[buf][r0 + 8][k8 + tg]);
                a[mi][2] = __float_as_uint(As[buf][r0][k8 + tg + 4]);
                a[mi][3] = __float_as_uint(As[buf][r0 + 8][k8 + tg + 4]);
            }
            uint32_t b[8][2];
#pragma unroll
            for (int ni = 0; ni < 8; ni++) {
                b[ni][0] = __float_as_uint(Bs[buf][k8 + tg][ni * 8 + g]);
                b[ni][1] = __float_as_uint(Bs[buf][k8 + tg + 4][ni * 8 + g]);
            }
#pragma unroll
            for (int mi = 0; mi < 2; mi++)
#pragma unroll
                for (int ni = 0; ni < 8; ni++)
                    mma_tf32(c[mi][ni], a[mi], b[ni]);
        }
        buf ^= 1;
    }

    const bool split = (gridDim.y > 1);
#pragma unroll
    for (int mi = 0; mi < 2; mi++) {
#pragma unroll
        for (int rr = 0; rr < 2; rr++) {
            int m = m0 + warp_m + mi * 16 + g + rr * 8;
            float dv2 = 0.0f;
            if (dvec) { float w = dvec[m]; dv2 = w * w; }
#pragma unroll
            for (int ni = 0; ni < 8; ni++) {
                int n = ni * 8 + tg * 2;
                float v0 = c[mi][ni][rr * 2 + 0];
                float v1 = c[mi][ni][rr * 2 + 1];
                if (split) {
                    atomicAdd(&C[(size_t)m * ldc + n],     v0);
                    atomicAdd(&C[(size_t)m * ldc + n + 1], v1);
                } else {
                    if (bias)  { v0 += bias[n]; v1 += bias[n + 1]; }
                    if (resid) { v0 += resid[(size_t)m * ldr + n];
                                 v1 += resid[(size_t)m * ldr + n + 1]; }
                    if (act)   { v0 = fmaxf(v0, 0.0f); v1 = fmaxf(v1, 0.0f); }
                    *(float2*)&C[(size_t)m * ldc + n] = make_float2(v0, v1);
                    if (dvec)
                        *(float2*)&C2[(size_t)m * 64 + n] =
                            make_float2(v0 * dv2, v1 * dv2);
                }
            }
        }
    }
}

// ---------------- rbf coupling + transpose (fast math) ----------------
__device__ __forceinline__ float exp_neg_04(float dist) {
    // exp(-dist/2.5) = 2^(dist * -log2(e)/2.5)
    float t  = dist * -0.5770780163555852f;
    float fn = floorf(t);
    float f  = t - fn;
    float p  = 1.5403530e-4f;
    p = fmaf(p, f, 1.33335581e-3f);
    p = fmaf(p, f, 9.61812911e-3f);
    p = fmaf(p, f, 5.55041087e-2f);
    p = fmaf(p, f, 2.40226507e-1f);
    p = fmaf(p, f, 6.93147181e-1f);
    p = fmaf(p, f, 1.0f);
    int n = (int)fn;
    n = n < -126 ? -126 : n;
    return p * __int_as_float((n + 127) << 23);
}

__global__ void rbf_kernel(const float* __restrict__ vert, const float* __restrict__ gp,
                           float* __restrict__ rbf, float* __restrict__ rbfT)
{
    __shared__ float tile[32][33];
    int tx = threadIdx.x, ty = threadIdx.y;
    int g = blockIdx.x * 32 + tx;
    int v = blockIdx.y * 32 + ty;
    float vx = vert[v * 3], vy = vert[v * 3 + 1], vz = vert[v * 3 + 2];
    float gx = gp[g * 3],  gy = gp[g * 3 + 1],  gz = gp[g * 3 + 2];
    float dx = vx - gx, dy = vy - gy, dz = vz - gz;
    float d2 = fmaf(dx, dx, fmaf(dy, dy, dz * dz));
    d2 = fmaxf(d2, 1e-24f);
    float rs;
    asm("rsqrt.approx.f32 %0, %1;" : "=f"(rs) : "f"(d2));
    float r = exp_neg_04(d2 * rs);
    rbf[(size_t)v * NG + g] = r;
    tile[ty][tx] = r;
    __syncthreads();
    int g2 = blockIdx.x * 32 + ty;
    int v2 = blockIdx.y * 32 + tx;
    rbfT[(size_t)g2 * NV + v2] = tile[tx][ty];
}

// ---------------- transpose evecs ----------------
__global__ void transpose_kernel(const float* __restrict__ in, float* __restrict__ out)
{
    __shared__ float t[32][33];
    int x = blockIdx.x * 32 + threadIdx.x;   // k
    int y = blockIdx.y * 32 + threadIdx.y;   // v
    t[threadIdx.y][threadIdx.x] = in[(size_t)y * 128 + x];
    __syncthreads();
    int ox = blockIdx.y * 32 + threadIdx.x;  // v
    int oy = blockIdx.x * 32 + threadIdx.y;  // k
    out[(size_t)oy * NV + ox] = t[threadIdx.x][threadIdx.y];
}

// ---------------- spectral / elementwise ----------------
__global__ void massx_kernel(const float* __restrict__ y, const float* __restrict__ mass,
                             float* __restrict__ f, float* __restrict__ mx)
{
    int gid = blockIdx.x * 256 + threadIdx.x;   // NV*64
    int v = gid >> 6, d = gid & 63;
    float x = y[gid];
    f[v * 192 + d] = x;
    mx[gid] = mass[v] * x;
}

__global__ void cs_kernel(const float* __restrict__ xs, const float* __restrict__ evals,
                          const float* __restrict__ t, float* __restrict__ cs)
{
    int gid = blockIdx.x * 256 + threadIdx.x;   // KK*64
    int k = gid >> 6, d = gid & 63;
    cs[gid] = expf(-evals[k] * fmaxf(t[d], 1e-8f)) * xs[gid];
}

__global__ void wcat_kernel(const float* __restrict__ are, const float* __restrict__ aim,
                            float* __restrict__ W)
{
    int gid = blockIdx.x * 256 + threadIdx.x;   // KK*64
    int k = gid >> 6, d = gid & 63;
    float wre, wim;
    if (k < 64) { wre = are[k * 64 + d];         wim = aim[k * 64 + d]; }
    else        { wre = -aim[(k - 64) * 64 + d]; wim = are[(k - 64) * 64 + d]; }
    W[gid]           = wre;
    W[KK * 64 + gid] = wim;
}

__global__ void gfeat_kernel(const float* __restrict__ cat, const float* __restrict__ b2,
                             float* __restrict__ f)
{
    int gid = blockIdx.x * 256 + threadIdx.x;   // NV*64
    int v = gid >> 6, d = gid & 63;
    float gx = cat[v * 128 + d];
    float gy = cat[v * 128 + 64 + d];
    float bre = b2[gid];
    float bim = b2[NV * 64 + gid];
    f[v * 192 + 128 + d] = tanhf(gx * bre + gy * bim);
}

// ---------------- GCN helpers (sparse path) ----------------
__global__ void deg_kernel(const int* __restrict__ dst, float* __restrict__ deg)
{
    int e = blockIdx.x * 256 + threadIdx.x;
    atomicAdd(&deg[dst[e]], 1.0f);
}
__global__ void dinv_kernel(const float* __restrict__ deg, float* __restrict__ dinv)
{
    int i = blockIdx.x * 256 + threadIdx.x;
    dinv[i] = rsqrtf(deg[i] + 1.0f);
}
__global__ void edge_kernel(const int* __restrict__ src, const int* __restrict__ dst,
                            const float* __restrict__ hw, const float* __restrict__ dinv,
                            float* __restrict__ agg)
{
    int e = blockIdx.x * 4 + (threadIdx.x >> 6);
    int d = threadIdx.x & 63;
    int s = src[e], t = dst[e];
    atomicAdd(&agg[t * 64 + d], hw[s * 64 + d] * dinv[s] * dinv[t]);
}
__global__ void finalize_kernel(const float* __restrict__ agg, const float* __restrict__ b,
                                float* __restrict__ out, int relu)
{
    int gid = blockIdx.x * 256 + threadIdx.x;   // NG*64
    int d = gid & 63;
    float v = agg[gid] + b[d];
    out[gid] = relu ? fmaxf(v, 0.0f) : v;
}

// ---------------- head / tail ----------------
__global__ void lin1_kernel(const float* __restrict__ sx, const float* __restrict__ w,
                            const float* __restrict__ b, float* __restrict__ y)
{
    int gid = blockIdx.x * 256 + threadIdx.x;   // NV*64
    int v = gid >> 6, d = gid & 63;
    float acc = b[d];
#pragma unroll
    for (int j = 0; j < 5; j++) acc += sx[v * 5 + j] * w[j * 64 + d];
    y[gid] = acc;
}

__global__ void out_kernel(const float* __restrict__ y, const float* __restrict__ w,
                           const float* __restrict__ b, float* __restrict__ out)
{
    int gid = blockIdx.x * 256 + threadIdx.x;   // NV*8
    int v = gid >> 3, c = gid & 7;
    float acc = b[c];
#pragma unroll 8
    for (int d = 0; d < 64; d++) acc += y[v * 64 + d] * w[d * 8 + c];
    out[gid] = acc;
}

// ---------------- host ----------------
extern "C" void kernel_launch(void* const* d_in, const int* in_sizes, int n_in,
                              void* d_out, int out_size)
{
    static bool inited = false;
    static float *p_rbf, *p_rbfT, *p_f, *p_y, *p_cat, *p_b2, *p_h1, *p_h2, *p_mx,
                 *p_xs, *p_cs, *p_W, *p_GE, *p_eT, *p_gx, *p_hw, *p_agg, *p_hg,
                 *p_gx2, *p_deg, *p_dinv;
    if (!inited) {
        cudaGetSymbolAddress((void**)&p_rbf,  g_rbf);
        cudaGetSymbolAddress((void**)&p_rbfT, g_rbfT);
        cudaGetSymbolAddress((void**)&p_f,    g_f);
        cudaGetSymbolAddress((void**)&p_y,    g_y);
        cudaGetSymbolAddress((void**)&p_cat,  g_cat);
        cudaGetSymbolAddress((void**)&p_b2,   g_b2);
        cudaGetSymbolAddress((void**)&p_h1,   g_h1);
        cudaGetSymbolAddress((void**)&p_h2,   g_h2);
        cudaGetSymbolAddress((void**)&p_mx,   g_mx);
        cudaGetSymbolAddress((void**)&p_xs,   g_xs);
        cudaGetSymbolAddress((void**)&p_cs,   g_cs);
        cudaGetSymbolAddress((void**)&p_W,    g_W);
        cudaGetSymbolAddress((void**)&p_GE,   g_GE);
        cudaGetSymbolAddress((void**)&p_eT,   g_eT);
        cudaGetSymbolAddress((void**)&p_gx,   g_gx);
        cudaGetSymbolAddress((void**)&p_hw,   g_hw);
        cudaGetSymbolAddress((void**)&p_agg,  g_agg);
        cudaGetSymbolAddress((void**)&p_hg,   g_hg);
        cudaGetSymbolAddress((void**)&p_gx2,  g_gx2);
        cudaGetSymbolAddress((void**)&p_deg,  g_deg);
        cudaGetSymbolAddress((void**)&p_dinv, g_dinv);
        inited = true;
    }

    const float* surf_x    = (const float*)d_in[0];
    const float* mass      = (const float*)d_in[1];
    const float* evals     = (const float*)d_in[2];
    const float* evecs     = (const float*)d_in[3];
    const float* gradX     = (const float*)d_in[4];
    const float* gradY     = (const float*)d_in[5];
    const float* vertices  = (const float*)d_in[6];
    const float* graph_pos = (const float*)d_in[8];
    const float* lin1_w    = (const float*)d_in[9];
    const float* lin1_b    = (const float*)d_in[10];
    const float* last_w    = (const float*)d_in[13];
    const float* last_b    = (const float*)d_in[14];
    const float* diff_time = (const float*)d_in[15];
    const float* A_re      = (const float*)d_in[16];
    const float* A_im      = (const float*)d_in[17];
    const float* mlp_w0    = (const float*)d_in[18];
    const float* mlp_b0    = (const float*)d_in[19];
    const float* mlp_w1    = (const float*)d_in[20];
    const float* mlp_b1    = (const float*)d_in[21];
    const float* mlp_w2    = (const float*)d_in[22];
    const float* mlp_b2    = (const float*)d_in[23];
    const float* gcn_w1    = (const float*)d_in[24];
    const float* gcn_b1    = (const float*)d_in[25];
    const float* gcn_w2    = (const float*)d_in[26];
    const float* gcn_b2    = (const float*)d_in[27];
    const int*   eidx      = (const int*)d_in[28];
    const int*   e_src     = eidx;
    const int*   e_dst     = eidx + EE;
    float* out = (float*)d_out;

    // ---- setup ----
    rbf_kernel<<<dim3(NG / 32, NV / 32), dim3(32, 32)>>>(vertices, graph_pos, p_rbf, p_rbfT);

    cudaMemsetAsync(p_deg, 0, NG * sizeof(float));
    deg_kernel<<<EE / 256, 256>>>(e_dst, p_deg);
    dinv_kernel<<<NG / 256, 256>>>(p_deg, p_dinv);

    transpose_kernel<<<dim3(KK / 32, NV / 32), dim3(32, 32)>>>(evecs, p_eT);
    lin1_kernel<<<NV * 64 / 256, 256>>>(surf_x, lin1_w, lin1_b, p_y);   // -> y[0]

    // GE = [gradX@evecs ; gradY@evecs]
    gemm64<<<dim3(NV / 128, 1, 4), 128>>>(
        gradX, gradY, /*zA=*/2, NV,
        evecs, evecs + 64, 128,
        p_GE, /*coff1=*/64, /*coff2=*/NV * 128, /*ldc=*/128,
        NV, NV, nullptr, nullptr, 0, 0, nullptr, nullptr);

    for (int blk = 0; blk < NBLK; blk++) {
        const float* t   = diff_time + blk * 64;
        const float* are = A_re + blk * 64 * 64;
        const float* aim = A_im + blk * 64 * 64;
        const float* w0  = mlp_w0 + blk * 192 * 64;
        const float* b0  = mlp_b0 + blk * 64;
        const float* w1  = mlp_w1 + blk * 64 * 64;
        const float* b1  = mlp_b1 + blk * 64;
        const float* w2  = mlp_w2 + blk * 64 * 64;
        const float* b2m = mlp_b2 + blk * 64;
        const float* gw1 = gcn_w1 + blk * 64 * 64;
        const float* gb1 = gcn_b1 + blk * 64;
        const float* gw2 = gcn_w2 + blk * 64 * 64;
        const float* gb2 = gcn_b2 + blk * 64;
        float* yA = p_y + (blk & 1) * NV * 64;        // read
        float* yB = p_y + (1 - (blk & 1)) * NV * 64;  // write

        // x -> f[:,0:64], mx = mass * x
        massx_kernel<<<NV * 64 / 256, 256>>>(yA, mass, p_f, p_mx);

        // xs = evecsT @ mx  (split-K 8)
        cudaMemsetAsync(p_xs, 0, KK * 64 * sizeof(float));
        gemm64<<<dim3(1, 8, 1), 128>>>(
            p_eT, p_eT, 0, NV, p_mx, p_mx, 64,
            p_xs, 0, 0, 64, NV, NV / 8, nullptr, nullptr, 0, 0, nullptr, nullptr);
        cs_kernel<<<KK * 64 / 256, 256>>>(p_xs, evals, t, p_cs);

        // x_diff = evecs @ cs -> f[:,64:128]
        gemm64<<<dim3(NV / 128, 1, 1), 128>>>(
            evecs, evecs, 0, 128, p_cs, p_cs, 64,
            p_f + 64, 0, 0, 192, KK, KK, nullptr, nullptr, 0, 0, nullptr, nullptr);

        // gX|gY = GE @ cs
        gemm64<<<dim3(NV / 128, 1, 2), 128>>>(
            p_GE, p_GE + NV * 128, /*zA=*/1, 128, p_cs, p_cs, 64,
            p_cat, 64, 0, 128, KK, KK, nullptr, nullptr, 0, 0, nullptr, nullptr);

        // b_re|b_im = cat @ [Wre|Wim]
        wcat_kernel<<<KK * 64 / 256, 256>>>(are, aim, p_W);
        gemm64<<<dim3(NV / 128, 1, 2), 128>>>(
            p_cat, p_cat, 0, 128, p_W, p_W + KK * 64, 64,
            p_b2, NV * 64, 0, 64, KK, KK, nullptr, nullptr, 0, 0, nullptr, nullptr);

        gfeat_kernel<<<NV * 64 / 256, 256>>>(p_cat, p_b2, p_f);

        // MLP
        gemm64<<<dim3(NV / 128, 1, 1), 128>>>(
            p_f, p_f, 0, 192, w0, w0, 64, p_h1, 0, 0, 64, 192, 192,
            b0, nullptr, 0, 1, nullptr, nullptr);
        gemm64<<<dim3(NV / 128, 1, 1), 128>>>(
            p_h1, p_h1, 0, 64, w1, w1, 64, p_h2, 0, 0, 64, 64, 64,
            b1, nullptr, 0, 1, nullptr, nullptr);
        gemm64<<<dim3(NV / 128, 1, 1), 128>>>(
            p_h2, p_h2, 0, 64, w2, w2, 64, p_f, 0, 0, 192, 64, 64,
            b2m, p_f, 192, 0, nullptr, nullptr);

        // gx = rbf^T @ diff_x (split-K 8)
        cudaMemsetAsync(p_gx, 0, NG * 64 * sizeof(float));
        gemm64<<<dim3(NG / 128, 8, 1), 128>>>(
            p_rbfT, p_rbfT, 0, NV, p_f, p_f, 192,
            p_gx, 0, 0, 64, NV, NV / 8, nullptr, nullptr, 0, 0, nullptr, nullptr);

        // GCN layer 1: hw = gx@W1 (+ fused self-loop into agg), edges, relu
        gemm64<<<dim3(NG / 128, 1, 1), 128>>>(
            p_gx, p_gx, 0, 64, gw1, gw1, 64, p_hw, 0, 0, 64, 64, 64,
            nullptr, nullptr, 0, 0, p_dinv, p_agg);
        edge_kernel<<<EE / 4, 256>>>(e_src, e_dst, p_hw, p_dinv, p_agg);
        finalize_kernel<<<NG * 64 / 256, 256>>>(p_agg, gb1, p_hg, 1);

        // GCN layer 2 (no relu)
        gemm64<<<dim3(NG / 128, 1, 1), 128>>>(
            p_hg, p_hg, 0, 64, gw2, gw2, 64, p_hw, 0, 0, 64, 64, 64,
            nullptr, nullptr, 0, 0, p_dinv, p_agg);
        edge_kernel<<<EE / 4, 256>>>(e_src, e_dst, p_hw, p_dinv, p_agg);
        finalize_kernel<<<NG * 64 / 256, 256>>>(p_agg, gb2, p_gx2, 0);

        // diff_x = rbf @ gx2 -> yB (split-K 4)
        cudaMemsetAsync(yB, 0, NV * 64 * sizeof(float));
        gemm64<<<dim3(NV / 128, 4, 1), 128>>>(
            p_rbf, p_rbf, 0, NG, p_gx2, p_gx2, 64,
            yB, 0, 0, 64, NG, NG / 4, nullptr, nullptr, 0, 0, nullptr, nullptr);
    }

    // final: out = y[0] @ last_w + last_b   (after 4 blocks result is in buffer 0)
    out_kernel<<<(NV * 8) / 256, 256>>>(p_y, last_w, last_b, out);
}

// round 6
// speedup vs baseline: 2.0708x; 1.1070x over previous
#include <cuda_runtime.h>
#include <math.h>
#include <stdint.h>

#define NV 4096
#define NG 2048
#define DD 64
#define KK 128
#define NBLK 4
#define EE 32768

// ---------------- scratch (device globals; no allocation allowed) ----------------
__device__ float g_rbf [NV * NG];        // [NV, NG]
__device__ float g_rbfT[NG * NV];        // [NG, NV]
__device__ float g_f   [NV * 192];       // [NV, 192] = [x | x_diff | gfeat]
__device__ float g_y   [2 * NV * 64];    // double-buffered diff_x
__device__ float g_cat [NV * 128];       // [gX | gY]
__device__ float g_b2  [2 * NV * 64];    // [b_re ; b_im]
__device__ float g_mx  [NV * 64];        // mass * x
__device__ float g_xs  [KK * 64];
__device__ float g_cs  [KK * 64];
__device__ float g_W   [NBLK * 2 * KK * 64];  // per-block [Wre ; Wim]
__device__ float g_GE  [2 * NV * 128];   // [gradX@evecs ; gradY@evecs]
__device__ float g_eT  [KK * NV];        // evecs^T
__device__ float g_gx  [NG * 64];
__device__ float g_hw  [NG * 64];
__device__ float g_agg [NG * 64];
__device__ float g_agg2[NG * 64];
__device__ float g_deg [NG];
__device__ float g_dinv[NG];

// ---------------- tf32 helpers ----------------
__device__ __forceinline__ float tf32r(float x) {
    uint32_t r;
    asm("cvt.rna.tf32.f32 %0, %1;" : "=r"(r) : "f"(x));
    return __uint_as_float(r);
}
__device__ __forceinline__ void mma_tf32(float* c, const uint32_t* a, const uint32_t* b) {
    asm volatile(
        "mma.sync.aligned.m16n8k8.row.col.f32.tf32.tf32.f32 "
        "{%0,%1,%2,%3}, {%4,%5,%6,%7}, {%8,%9}, {%0,%1,%2,%3};"
        : "+f"(c[0]), "+f"(c[1]), "+f"(c[2]), "+f"(c[3])
        : "r"(a[0]), "r"(a[1]), "r"(a[2]), "r"(a[3]), "r"(b[0]), "r"(b[1]));
}

// per-z slice descriptors (A, C, ldc each selected by blockIdx.z)
struct Sl {
    const float* A[4];
    float*       C[4];
    int          ldc[4];
};

// ---------------- generic N=64 GEMM (tf32 MMA), BM=128, 128 threads -----------
// Register-prefetch double-buffered; one __syncthreads per k-tile.
// abias: A-load transform  a = relu(a + abias[k])   (GCN layer-2 input fusion)
// bbias: B-load transform  b = b + bbias[n]         (agg2 + gb2 fusion)
// dvec/C2: extra output C2[m*64+n] = v * dvec[m]^2  (GCN self-loop fusion)
// gridDim.y > 1 => split-K atomicAdd (caller zero-inits C).
__global__ __launch_bounds__(128) void gemm64(
    Sl sl, int lda,
    const float* __restrict__ B0, const float* __restrict__ B1, int ldb,
    int KB, int kchunk,
    const float* __restrict__ bias,
    const float* __restrict__ resid, int ldr, int act,
    const float* __restrict__ dvec, float* __restrict__ C2,
    const float* __restrict__ abias, const float* __restrict__ bbias)
{
    __shared__ float As[2][128][36];
    __shared__ float Bs[2][32][72];

    const int z = blockIdx.z;
    const float* A = sl.A[z];
    const float* B = (z & 1) ? B1 : B0;
    float* C = sl.C[z];
    const int ldc = sl.ldc[z];

    const int tid    = threadIdx.x;
    const int warp   = tid >> 5;
    const int lane   = tid & 31;
    const int g      = lane >> 2;
    const int tg     = lane & 3;
    const int m0     = blockIdx.x * 128;
    const int warp_m = warp * 32;
    const int kbeg   = blockIdx.y * kchunk;
    const int ntile  = kchunk >> 5;

    const int am = tid >> 3;
    const int ak = (tid & 7) * 4;
    const int bk = tid >> 4;
    const int bn = (tid & 15) * 4;

    float4 bb = make_float4(0.f, 0.f, 0.f, 0.f);
    if (bbias) bb = *(const float4*)(bbias + bn);

    float4 rA[8], rB[4];
    float c[2][8][4];
#pragma unroll
    for (int mi = 0; mi < 2; mi++)
#pragma unroll
        for (int ni = 0; ni < 8; ni++)
#pragma unroll
            for (int r = 0; r < 4; r++) c[mi][ni][r] = 0.0f;

    {   // prologue tile 0
        const float* ap = A + (size_t)(m0 + am) * lda + kbeg + ak;
        const float* bp = B + (size_t)(kbeg + bk) * ldb + bn;
#pragma unroll
        for (int i = 0; i < 8; i++) rA[i] = *(const float4*)(ap + (size_t)(i * 16) * lda);
#pragma unroll
        for (int i = 0; i < 4; i++) rB[i] = *(const float4*)(bp + (size_t)(i * 8) * ldb);
    }

    int buf = 0;
    for (int it = 0; it < ntile; it++) {
        const int kst = kbeg + it * 32;
#pragma unroll
        for (int i = 0; i < 8; i++) {
            float4 v = rA[i];
            if (abias) {
                float4 ab = *(const float4*)(abias + kst + ak);
                v.x = fmaxf(v.x + ab.x, 0.f); v.y = fmaxf(v.y + ab.y, 0.f);
                v.z = fmaxf(v.z + ab.z, 0.f); v.w = fmaxf(v.w + ab.w, 0.f);
            }
            v.x = tf32r(v.x); v.y = tf32r(v.y); v.z = tf32r(v.z); v.w = tf32r(v.w);
            *(float4*)&As[buf][am + i * 16][ak] = v;
        }
#pragma unroll
        for (int i = 0; i < 4; i++) {
            float4 v = rB[i];
            v.x += bb.x; v.y += bb.y; v.z += bb.z; v.w += bb.w;
            v.x = tf32r(v.x); v.y = tf32r(v.y); v.z = tf32r(v.z); v.w = tf32r(v.w);
            *(float4*)&Bs[buf][bk + i * 8][bn] = v;
        }
        __syncthreads();

        if (it + 1 < ntile) {
            int kb = kbeg + (it + 1) * 32;
            const float* ap = A + (size_t)(m0 + am) * lda + kb + ak;
            const float* bp = B + (size_t)(kb + bk) * ldb + bn;
#pragma unroll
            for (int i = 0; i < 8; i++) rA[i] = *(const float4*)(ap + (size_t)(i * 16) * lda);
#pragma unroll
            for (int i = 0; i < 4; i++) rB[i] = *(const float4*)(bp + (size_t)(i * 8) * ldb);
        }

#pragma unroll
        for (int k8 = 0; k8 < 32; k8 += 8) {
            uint32_t a[2][4];
#pragma unroll
            for (int mi = 0; mi < 2; mi++) {
                int r0 = warp_m + mi * 16 + g;
                a[mi][0] = __float_as_uint(As[buf][r0][k8 + tg]);
                a[mi][1] = __float_as_uint(As[buf][r0 + 8][k8 + tg]);
                a[mi][2] = __float_as_uint(As[buf][r0][k8 + tg + 4]);
                a[mi][3] = __float_as_uint(As[buf][r0 + 8][k8 + tg + 4]);
            }
            uint32_t b[8][2];
#pragma unroll
            for (int ni = 0; ni < 8; ni++) {
                b[ni][0] = __float_as_uint(Bs[buf][k8 + tg][ni * 8 + g]);
                b[ni][1] = __float_as_uint(Bs[buf][k8 + tg + 4][ni * 8 + g]);
            }
#pragma unroll
            for (int mi = 0; mi < 2; mi++)
#pragma unroll
                for (int ni = 0; ni < 8; ni++)
                    mma_tf32(c[mi][ni], a[mi], b[ni]);
        }
        buf ^= 1;
    }

    const bool split = (gridDim.y > 1);
#pragma unroll
    for (int mi = 0; mi < 2; mi++) {
#pragma unroll
        for (int rr = 0; rr < 2; rr++) {
            int m = m0 + warp_m + mi * 16 + g + rr * 8;
            float dv2 = 0.0f;
            if (dvec) { float w = dvec[m]; dv2 = w * w; }
#pragma unroll
            for (int ni = 0; ni < 8; ni++) {
                int n = ni * 8 + tg * 2;
                float v0 = c[mi][ni][rr * 2 + 0];
                float v1 = c[mi][ni][rr * 2 + 1];
                if (split) {
                    atomicAdd(&C[(size_t)m * ldc + n],     v0);
                    atomicAdd(&C[(size_t)m * ldc + n + 1], v1);
                } else {
                    if (bias)  { v0 += bias[n]; v1 += bias[n + 1]; }
                    if (resid) { v0 += resid[(size_t)m * ldr + n];
                                 v1 += resid[(size_t)m * ldr + n + 1]; }
                    if (act)   { v0 = fmaxf(v0, 0.0f); v1 = fmaxf(v1, 0.0f); }
                    *(float2*)&C[(size_t)m * ldc + n] = make_float2(v0, v1);
                    if (dvec)
                        *(float2*)&C2[(size_t)m * 64 + n] =
                            make_float2(v0 * dv2, v1 * dv2);
                }
            }
        }
    }
}

// ---------------- fused 3-layer MLP (one launch): f -> relu -> relu -> +x ------
// h1/h2 live in the smem A-buffers between phases (own-warp rows only).
__global__ __launch_bounds__(128) void mlp_kernel(
    float* __restrict__ f,                         // [NV,192]; writes cols 0:64
    const float* __restrict__ w0, const float* __restrict__ b0,
    const float* __restrict__ w1, const float* __restrict__ b1,
    const float* __restrict__ w2, const float* __restrict__ b2)
{
    __shared__ float As[2][128][36];
    __shared__ float Bs[2][32][72];

    const int tid = threadIdx.x, warp = tid >> 5, lane = tid & 31;
    const int g = lane >> 2, tg = lane & 3;
    const int m0 = blockIdx.x * 128, warp_m = warp * 32;
    const int am = tid >> 3, ak = (tid & 7) * 4;
    const int bk = tid >> 4, bn = (tid & 15) * 4;

    float c[2][8][4];
#pragma unroll
    for (int mi = 0; mi < 2; mi++)
#pragma unroll
        for (int ni = 0; ni < 8; ni++)
#pragma unroll
            for (int r = 0; r < 4; r++) c[mi][ni][r] = 0.0f;

    // ---- phase 1: h1 = relu(f @ w0 + b0), K=192 streamed (6 tiles) ----
    float4 rA[8], rB[4];
    {
        const float* ap = f + (size_t)(m0 + am) * 192 + ak;
        const float* bp = w0 + (size_t)bk * 64 + bn;
#pragma unroll
        for (int i = 0; i < 8; i++) rA[i] = *(const float4*)(ap + (size_t)(i * 16) * 192);
#pragma unroll
        for (int i = 0; i < 4; i++) rB[i] = *(const float4*)(bp + (size_t)(i * 8) * 64);
    }
    int buf = 0;
    for (int it = 0; it < 6; it++) {
#pragma unroll
        for (int i = 0; i < 8; i++) {
            float4 v = rA[i];
            v.x = tf32r(v.x); v.y = tf32r(v.y); v.z = tf32r(v.z); v.w = tf32r(v.w);
            *(float4*)&As[buf][am + i * 16][ak] = v;
        }
#pragma unroll
        for (int i = 0; i < 4; i++) {
            float4 v = rB[i];
            v.x = tf32r(v.x); v.y = tf32r(v.y); v.z = tf32r(v.z); v.w = tf32r(v.w);
            *(float4*)&Bs[buf][bk + i * 8][bn] = v;
        }
        __syncthreads();
        if (it + 1 < 6) {
            int kb = (it + 1) * 32;
            const float* ap = f + (size_t)(m0 + am) * 192 + kb + ak;
            const float* bp = w0 + (size_t)(kb + bk) * 64 + bn;
#pragma unroll
            for (int i = 0; i < 8; i++) rA[i] = *(const float4*)(ap + (size_t)(i * 16) * 192);
#pragma unroll
            for (int i = 0; i < 4; i++) rB[i] = *(const float4*)(bp + (size_t)(i * 8) * 64);
        }
#pragma unroll
        for (int k8 = 0; k8 < 32; k8 += 8) {
            uint32_t a[2][4];
#pragma unroll
            for (int mi = 0; mi < 2; mi++) {
                int r0 = warp_m + mi * 16 + g;
                a[mi][0] = __float_as_uint(As[buf][r0][k8 + tg]);
                a[mi][1] = __float_as_uint(As[buf][r0 + 8][k8 + tg]);
                a[mi][2] = __float_as_uint(As[buf][r0][k8 + tg + 4]);
                a[mi][3] = __float_as_uint(As[buf][r0 + 8][k8 + tg + 4]);
            }
            uint32_t b[8][2];
#pragma unroll
            for (int ni = 0; ni < 8; ni++) {
                b[ni][0] = __float_as_uint(Bs[buf][k8 + tg][ni * 8 + g]);
                b[ni][1] = __float_as_uint(Bs[buf][k8 + tg + 4][ni * 8 + g]);
            }
#pragma unroll
            for (int mi = 0; mi < 2; mi++)
#pragma unroll
                for (int ni = 0; ni < 8; ni++)
                    mma_tf32(c[mi][ni], a[mi], b[ni]);
        }
        buf ^= 1;
    }
    // h1 -> As (own-warp rows; no barrier needed for A)
#pragma unroll
    for (int mi = 0; mi < 2; mi++)
#pragma unroll
        for (int rr = 0; rr < 2; rr++) {
            int ml = warp_m + mi * 16 + g + rr * 8;
#pragma unroll
            for (int ni = 0; ni < 8; ni++) {
                int n = ni * 8 + tg * 2;
                float v0 = fmaxf(c[mi][ni][rr * 2 + 0] + b0[n], 0.f);
                float v1 = fmaxf(c[mi][ni][rr * 2 + 1] + b0[n + 1], 0.f);
                *(float2*)&As[n >> 5][ml][n & 31] = make_float2(tf32r(v0), tf32r(v1));
            }
        }
    __syncthreads();   // all Bs reads from phase 1 done before restaging

    // ---- phase 2: h2 = relu(h1 @ w1 + b1), K=64 (both tiles staged) ----
#pragma unroll
    for (int t = 0; t < 2; t++)
#pragma unroll
        for (int i = 0; i < 4; i++) {
            float4 v = *(const float4*)(w1 + (size_t)(t * 32 + bk + i * 8) * 64 + bn);
            v.x = tf32r(v.x); v.y = tf32r(v.y); v.z = tf32r(v.z); v.w = tf32r(v.w);
            *(float4*)&Bs[t][bk + i * 8][bn] = v;
        }
    __syncthreads();
#pragma unroll
    for (int mi = 0; mi < 2; mi++)
#pragma unroll
        for (int ni = 0; ni < 8; ni++)
#pragma unroll
            for (int r = 0; r < 4; r++) c[mi][ni][r] = 0.0f;
#pragma unroll
    for (int kt = 0; kt < 2; kt++)
#pragma unroll
        for (int k8 = 0; k8 < 32; k8 += 8) {
            uint32_t a[2][4];
#pragma unroll
            for (int mi = 0; mi < 2; mi++) {
                int r0 = warp_m + mi * 16 + g;
                a[mi][0] = __float_as_uint(As[kt][r0][k8 + tg]);
                a[mi][1] = __float_as_uint(As[kt][r0 + 8][k8 + tg]);
                a[mi][2] = __float_as_uint(As[kt][r0][k8 + tg + 4]);
                a[mi][3] = __float_as_uint(As[kt][r0 + 8][k8 + tg + 4]);
            }
            uint32_t b[8][2];
#pragma unroll
            for (int ni = 0; ni < 8; ni++) {
                b[ni][0] = __float_as_uint(Bs[kt][k8 + tg][ni * 8 + g]);
                b[ni][1] = __float_as_uint(Bs[kt][k8 + tg + 4][ni * 8 + g]);
            }
#pragma unroll
            for (int mi = 0; mi < 2; mi++)
#pragma unroll
                for (int ni = 0; ni < 8; ni++)
                    mma_tf32(c[mi][ni], a[mi], b[ni]);
        }
    // h2 -> As (own-warp rows)
#pragma unroll
    for (int mi = 0; mi < 2; mi++)
#pragma unroll
        for (int rr = 0; rr < 2; rr++) {
            int ml = warp_m + mi * 16 + g + rr * 8;
#pragma unroll
            for (int ni = 0; ni < 8; ni++) {
                int n = ni * 8 + tg * 2;
                float v0 = fmaxf(c[mi][ni][rr * 2 + 0] + b1[n], 0.f);
                float v1 = fmaxf(c[mi][ni][rr * 2 + 1] + b1[n + 1], 0.f);
                *(float2*)&As[n >> 5][ml][n & 31] = make_float2(tf32r(v0), tf32r(v1));
            }
        }
    __syncthreads();   // all Bs reads from phase 2 done before restaging

    // ---- phase 3: x' = h2 @ w2 + b2 + x ----
#pragma unroll
    for (int t = 0; t < 2; t++)
#pragma unroll
        for (int i = 0; i < 4; i++) {
            float4 v = *(const float4*)(w2 + (size_t)(t * 32 + bk + i * 8) * 64 + bn);
            v.x = tf32r(v.x); v.y = tf32r(v.y); v.z = tf32r(v.z); v.w = tf32r(v.w);
            *(float4*)&Bs[t][bk + i * 8][bn] = v;
        }
    __syncthreads();
#pragma unroll
    for (int mi = 0; mi < 2; mi++)
#pragma unroll
        for (int ni = 0; ni < 8; ni++)
#pragma unroll
            for (int r = 0; r < 4; r++) c[mi][ni][r] = 0.0f;
#pragma unroll
    for (int kt = 0; kt < 2; kt++)
#pragma unroll
        for (int k8 = 0; k8 < 32; k8 += 8) {
            uint32_t a[2][4];
#pragma unroll
            for (int mi = 0; mi < 2; mi++) {
                int r0 = warp_m + mi * 16 + g;
                a[mi][0] = __float_as_uint(As[kt][r0][k8 + tg]);
                a[mi][1] = __float_as_uint(As[kt][r0 + 8][k8 + tg]);
                a[mi][2] = __float_as_uint(As[kt][r0][k8 + tg + 4]);
                a[mi][3] = __float_as_uint(As[kt][r0 + 8][k8 + tg + 4]);
            }
            uint32_t b[8][2];
#pragma unroll
            for (int ni = 0; ni < 8; ni++) {
                b[ni][0] = __float_as_uint(Bs[kt][k8 + tg][ni * 8 + g]);
                b[ni][1] = __float_as_uint(Bs[kt][k8 + tg + 4][ni * 8 + g]);
            }
#pragma unroll
            for (int mi = 0; mi < 2; mi++)
#pragma unroll
                for (int ni = 0; ni < 8; ni++)
                    mma_tf32(c[mi][ni], a[mi], b[ni]);
        }
#pragma unroll
    for (int mi = 0; mi < 2; mi++)
#pragma unroll
        for (int rr = 0; rr < 2; rr++) {
            int m = m0 + warp_m + mi * 16 + g + rr * 8;
#pragma unroll
            for (int ni = 0; ni < 8; ni++) {
                int n = ni * 8 + tg * 2;
                float v0 = c[mi][ni][rr * 2 + 0] + b2[n]     + f[(size_t)m * 192 + n];
                float v1 = c[mi][ni][rr * 2 + 1] + b2[n + 1] + f[(size_t)m * 192 + n + 1];
                *(float2*)&f[(size_t)m * 192 + n] = make_float2(v0, v1);
            }
        }
}

// ---------------- rbf coupling + transpose (fast math) ----------------
__device__ __forceinline__ float exp_neg_04(float dist) {
    float t  = dist * -0.5770780163555852f;
    float fn = floorf(t);
    float fr = t - fn;
    float p  = 1.5403530e-4f;
    p = fmaf(p, fr, 1.33335581e-3f);
    p = fmaf(p, fr, 9.61812911e-3f);
    p = fmaf(p, fr, 5.55041087e-2f);
    p = fmaf(p, fr, 2.40226507e-1f);
    p = fmaf(p, fr, 6.93147181e-1f);
    p = fmaf(p, fr, 1.0f);
    int n = (int)fn;
    n = n < -126 ? -126 : n;
    return p * __int_as_float((n + 127) << 23);
}

__global__ void rbf_kernel(const float* __restrict__ vert, const float* __restrict__ gp,
                           float* __restrict__ rbf, float* __restrict__ rbfT)
{
    __shared__ float tile[32][33];
    int tx = threadIdx.x, ty = threadIdx.y;
    int g = blockIdx.x * 32 + tx;
    int v = blockIdx.y * 32 + ty;
    float vx = vert[v * 3], vy = vert[v * 3 + 1], vz = vert[v * 3 + 2];
    float gx = gp[g * 3],  gy = gp[g * 3 + 1],  gz = gp[g * 3 + 2];
    float dx = vx - gx, dy = vy - gy, dz = vz - gz;
    float d2 = fmaf(dx, dx, fmaf(dy, dy, dz * dz));
    d2 = fmaxf(d2, 1e-24f);
    float rs;
    asm("rsqrt.approx.f32 %0, %1;" : "=f"(rs) : "f"(d2));
    float r = exp_neg_04(d2 * rs);
    rbf[(size_t)v * NG + g] = r;
    tile[ty][tx] = r;
    __syncthreads();
    int g2 = blockIdx.x * 32 + ty;
    int v2 = blockIdx.y * 32 + tx;
    rbfT[(size_t)g2 * NV + v2] = tile[tx][ty];
}

// ---------------- transpose evecs ----------------
__global__ void transpose_kernel(const float* __restrict__ in, float* __restrict__ out)
{
    __shared__ float t[32][33];
    int x = blockIdx.x * 32 + threadIdx.x;
    int y = blockIdx.y * 32 + threadIdx.y;
    t[threadIdx.y][threadIdx.x] = in[(size_t)y * 128 + x];
    __syncthreads();
    int ox = blockIdx.y * 32 + threadIdx.x;
    int oy = blockIdx.x * 32 + threadIdx.y;
    out[(size_t)oy * NV + ox] = t[threadIdx.x][threadIdx.y];
}

// ---------------- elementwise (with fused zeroing) ----------------
__global__ void massx_kernel(const float* __restrict__ y, const float* __restrict__ mass,
                             float* __restrict__ f, float* __restrict__ mx,
                             float* __restrict__ yB, float* __restrict__ xs)
{
    int gid = blockIdx.x * 256 + threadIdx.x;   // NV*64
    int v = gid >> 6, d = gid & 63;
    float x = y[gid];
    f[v * 192 + d] = x;
    mx[gid] = mass[v] * x;
    yB[gid] = 0.0f;
    if (gid < KK * 64) xs[gid] = 0.0f;
}

__global__ void cs_kernel(const float* __restrict__ xs, const float* __restrict__ evals,
                          const float* __restrict__ t, float* __restrict__ cs,
                          float* __restrict__ gx)
{
    int gid = blockIdx.x * 256 + threadIdx.x;   // KK*64 + NG*64
    if (gid < KK * 64) {
        int k = gid >> 6, d = gid & 63;
        cs[gid] = expf(-evals[k] * fmaxf(t[d], 1e-8f)) * xs[gid];
    } else {
        gx[gid - KK * 64] = 0.0f;
    }
}

__global__ void wcat_kernel(const float* __restrict__ are, const float* __restrict__ aim,
                            float* __restrict__ W)
{
    int gid = blockIdx.x * 256 + threadIdx.x;   // NBLK*KK*64
    int blk = gid >> 13;
    int r = gid & 8191;
    int k = r >> 6, d = r & 63;
    const float* a_re = are + blk * 64 * 64;
    const float* a_im = aim + blk * 64 * 64;
    float wre, wim;
    if (k < 64) { wre = a_re[k * 64 + d];         wim = a_im[k * 64 + d]; }
    else        { wre = -a_im[(k - 64) * 64 + d]; wim = a_re[(k - 64) * 64 + d]; }
    float* Wb = W + blk * 2 * KK * 64;
    Wb[r]            = wre;
    Wb[KK * 64 + r]  = wim;
}

__global__ void gfeat_kernel(const float* __restrict__ cat, const float* __restrict__ b2,
                             float* __restrict__ f)
{
    int gid = blockIdx.x * 256 + threadIdx.x;   // NV*64
    int v = gid >> 6, d = gid & 63;
    float gx = cat[v * 128 + d];
    float gy = cat[v * 128 + 64 + d];
    float bre = b2[gid];
    float bim = b2[NV * 64 + gid];
    f[v * 192 + 128 + d] = tanhf(gx * bre + gy * bim);
}

// ---------------- GCN helpers (sparse path) ----------------
__global__ void deg_kernel(const int* __restrict__ dst, float* __restrict__ deg)
{
    int e = blockIdx.x * 256 + threadIdx.x;
    atomicAdd(&deg[dst[e]], 1.0f);
}
__global__ void dinv_kernel(const float* __restrict__ deg, float* __restrict__ dinv)
{
    int i = blockIdx.x * 256 + threadIdx.x;
    dinv[i] = rsqrtf(deg[i] + 1.0f);
}
__global__ void edge_kernel(const int* __restrict__ src, const int* __restrict__ dst,
                            const float* __restrict__ hw, const float* __restrict__ dinv,
                            float* __restrict__ agg)
{
    int e = blockIdx.x * 4 + (threadIdx.x >> 6);
    int d = threadIdx.x & 63;
    int s = src[e], t = dst[e];
    atomicAdd(&agg[t * 64 + d], hw[s * 64 + d] * dinv[s] * dinv[t]);
}

// ---------------- head / tail ----------------
__global__ void lin1_kernel(const float* __restrict__ sx, const float* __restrict__ w,
                            const float* __restrict__ b, float* __restrict__ y)
{
    int gid = blockIdx.x * 256 + threadIdx.x;   // NV*64
    int v = gid >> 6, d = gid & 63;
    float acc = b[d];
#pragma unroll
    for (int j = 0; j < 5; j++) acc += sx[v * 5 + j] * w[j * 64 + d];
    y[gid] = acc;
}

__global__ void out_kernel(const float* __restrict__ y, const float* __restrict__ w,
                           const float* __restrict__ b, float* __restrict__ out)
{
    int gid = blockIdx.x * 256 + threadIdx.x;   // NV*8
    int v = gid >> 3, c = gid & 7;
    float acc = b[c];
#pragma unroll 8
    for (int d = 0; d < 64; d++) acc += y[v * 64 + d] * w[d * 8 + c];
    out[gid] = acc;
}

// ---------------- host ----------------
static inline Sl sl1(const float* A, float* C, int ldc) {
    Sl s; for (int i = 0; i < 4; i++) { s.A[i] = A; s.C[i] = C; s.ldc[i] = ldc; }
    return s;
}

extern "C" void kernel_launch(void* const* d_in, const int* in_sizes, int n_in,
                              void* d_out, int out_size)
{
    static bool inited = false;
    static float *p_rbf, *p_rbfT, *p_f, *p_y, *p_cat, *p_b2, *p_mx,
                 *p_xs, *p_cs, *p_W, *p_GE, *p_eT, *p_gx, *p_hw, *p_agg, *p_agg2,
                 *p_deg, *p_dinv;
    if (!inited) {
        cudaGetSymbolAddress((void**)&p_rbf,  g_rbf);
        cudaGetSymbolAddress((void**)&p_rbfT, g_rbfT);
        cudaGetSymbolAddress((void**)&p_f,    g_f);
        cudaGetSymbolAddress((void**)&p_y,    g_y);
        cudaGetSymbolAddress((void**)&p_cat,  g_cat);
        cudaGetSymbolAddress((void**)&p_b2,   g_b2);
        cudaGetSymbolAddress((void**)&p_mx,   g_mx);
        cudaGetSymbolAddress((void**)&p_xs,   g_xs);
        cudaGetSymbolAddress((void**)&p_cs,   g_cs);
        cudaGetSymbolAddress((void**)&p_W,    g_W);
        cudaGetSymbolAddress((void**)&p_GE,   g_GE);
        cudaGetSymbolAddress((void**)&p_eT,   g_eT);
        cudaGetSymbolAddress((void**)&p_gx,   g_gx);
        cudaGetSymbolAddress((void**)&p_hw,   g_hw);
        cudaGetSymbolAddress((void**)&p_agg,  g_agg);
        cudaGetSymbolAddress((void**)&p_agg2, g_agg2);
        cudaGetSymbolAddress((void**)&p_deg,  g_deg);
        cudaGetSymbolAddress((void**)&p_dinv, g_dinv);
        inited = true;
    }

    const float* surf_x    = (const float*)d_in[0];
    const float* mass      = (const float*)d_in[1];
    const float* evals     = (const float*)d_in[2];
    const float* evecs     = (const float*)d_in[3];
    const float* gradX     = (const float*)d_in[4];
    const float* gradY     = (const float*)d_in[5];
    const float* vertices  = (const float*)d_in[6];
    const float* graph_pos = (const float*)d_in[8];
    const float* lin1_w    = (const float*)d_in[9];
    const float* lin1_b    = (const float*)d_in[10];
    const float* last_w    = (const float*)d_in[13];
    const float* last_b    = (const float*)d_in[14];
    const float* diff_time = (const float*)d_in[15];
    const float* A_re      = (const float*)d_in[16];
    const float* A_im      = (const float*)d_in[17];
    const float* mlp_w0    = (const float*)d_in[18];
    const float* mlp_b0    = (const float*)d_in[19];
    const float* mlp_w1    = (const float*)d_in[20];
    const float* mlp_b1    = (const float*)d_in[21];
    const float* mlp_w2    = (const float*)d_in[22];
    const float* mlp_b2    = (const float*)d_in[23];
    const float* gcn_w1    = (const float*)d_in[24];
    const float* gcn_b1    = (const float*)d_in[25];
    const float* gcn_w2    = (const float*)d_in[26];
    const float* gcn_b2    = (const float*)d_in[27];
    const int*   eidx      = (const int*)d_in[28];
    const int*   e_src     = eidx;
    const int*   e_dst     = eidx + EE;
    float* out = (float*)d_out;

    // ---- setup ----
    rbf_kernel<<<dim3(NG / 32, NV / 32), dim3(32, 32)>>>(vertices, graph_pos, p_rbf, p_rbfT);

    cudaMemsetAsync(p_deg, 0, NG * sizeof(float));
    deg_kernel<<<EE / 256, 256>>>(e_dst, p_deg);
    dinv_kernel<<<NG / 256, 256>>>(p_deg, p_dinv);

    transpose_kernel<<<dim3(KK / 32, NV / 32), dim3(32, 32)>>>(evecs, p_eT);
    lin1_kernel<<<NV * 64 / 256, 256>>>(surf_x, lin1_w, lin1_b, p_y);       // -> y[0]
    wcat_kernel<<<NBLK * KK * 64 / 256, 256>>>(A_re, A_im, p_W);            // all blocks

    // GE = [gradX@evecs(lo) ; gradX@evecs(hi) ; gradY@evecs(lo) ; gradY@evecs(hi)]
    {
        Sl s;
        s.A[0] = gradX; s.A[1] = gradX; s.A[2] = gradY; s.A[3] = gradY;
        s.C[0] = p_GE;           s.C[1] = p_GE + 64;
        s.C[2] = p_GE + NV*128;  s.C[3] = p_GE + NV*128 + 64;
        s.ldc[0] = s.ldc[1] = s.ldc[2] = s.ldc[3] = 128;
        gemm64<<<dim3(NV / 128, 1, 4), 128>>>(
            s, NV, evecs, evecs + 64, 128, NV, NV,
            nullptr, nullptr, 0, 0, nullptr, nullptr, nullptr, nullptr);
    }

    for (int blk = 0; blk < NBLK; blk++) {
        const float* t   = diff_time + blk * 64;
        const float* w0  = mlp_w0 + blk * 192 * 64;
        const float* b0  = mlp_b0 + blk * 64;
        const float* w1  = mlp_w1 + blk * 64 * 64;
        const float* b1  = mlp_b1 + blk * 64;
        const float* w2  = mlp_w2 + blk * 64 * 64;
        const float* b2m = mlp_b2 + blk * 64;
        const float* gw1 = gcn_w1 + blk * 64 * 64;
        const float* gb1 = gcn_b1 + blk * 64;
        const float* gw2 = gcn_w2 + blk * 64 * 64;
        const float* gb2 = gcn_b2 + blk * 64;
        const float* Wb  = p_W + blk * 2 * KK * 64;
        float* yA = p_y + (blk & 1) * NV * 64;        // read
        float* yB = p_y + (1 - (blk & 1)) * NV * 64;  // write

        // x -> f[:,0:64], mx = mass*x ; zero yB + xs
        massx_kernel<<<NV * 64 / 256, 256>>>(yA, mass, p_f, p_mx, yB, p_xs);

        // xs = evecsT @ mx  (split-K 16)
        gemm64<<<dim3(1, 16, 1), 128>>>(
            sl1(p_eT, p_xs, 64), NV, p_mx, p_mx, 64, NV, NV / 16,
            nullptr, nullptr, 0, 0, nullptr, nullptr, nullptr, nullptr);
        // cs = coef * xs ; zero gx
        cs_kernel<<<(KK * 64 + NG * 64) / 256, 256>>>(p_xs, evals, t, p_cs, p_gx);

        // [x_diff ; gX ; gY] = [evecs ; GE_X ; GE_Y] @ cs  (one z=3 launch)
        {
            Sl s;
            s.A[0] = evecs;        s.C[0] = p_f + 64;   s.ldc[0] = 192;
            s.A[1] = p_GE;         s.C[1] = p_cat;      s.ldc[1] = 128;
            s.A[2] = p_GE + NV*128; s.C[2] = p_cat + 64; s.ldc[2] = 128;
            s.A[3] = evecs;        s.C[3] = p_f + 64;   s.ldc[3] = 192;
            gemm64<<<dim3(NV / 128, 1, 3), 128>>>(
                s, 128, p_cs, p_cs, 64, KK, KK,
                nullptr, nullptr, 0, 0, nullptr, nullptr, nullptr, nullptr);
        }

        // b_re|b_im = cat @ [Wre|Wim]
        {
            Sl s;
            s.A[0] = p_cat; s.C[0] = p_b2;           s.ldc[0] = 64;
            s.A[1] = p_cat; s.C[1] = p_b2 + NV * 64; s.ldc[1] = 64;
            s.A[2] = p_cat; s.C[2] = p_b2;           s.ldc[2] = 64;
            s.A[3] = p_cat; s.C[3] = p_b2;           s.ldc[3] = 64;
            gemm64<<<dim3(NV / 128, 1, 2), 128>>>(
                s, 128, Wb, Wb + KK * 64, 64, KK, KK,
                nullptr, nullptr, 0, 0, nullptr, nullptr, nullptr, nullptr);
        }

        gfeat_kernel<<<NV * 64 / 256, 256>>>(p_cat, p_b2, p_f);

        // fused 3-layer MLP + residual (writes f[:,0:64])
        mlp_kernel<<<NV / 128, 128>>>(p_f, w0, b0, w1, b1, w2, b2m);

        // gx = rbf^T @ diff_x (split-K 8)
        gemm64<<<dim3(NG / 128, 8, 1), 128>>>(
            sl1(p_rbfT, p_gx, 64), NV, p_f, p_f, 192, NV, NV / 8,
            nullptr, nullptr, 0, 0, nullptr, nullptr, nullptr, nullptr);

        // GCN layer 1: hw1 = gx@W1 ; agg1 = selfloop (fused) + edges
        gemm64<<<dim3(NG / 128, 1, 1), 128>>>(
            sl1(p_gx, p_hw, 64), 64, gw1, gw1, 64, 64, 64,
            nullptr, nullptr, 0, 0, p_dinv, p_agg, nullptr, nullptr);
        edge_kernel<<<EE / 4, 256>>>(e_src, e_dst, p_hw, p_dinv, p_agg);

        // GCN layer 2: hw2 = relu(agg1 + gb1) @ W2 (A-loader fused) ; agg2 = selfloop + edges
        gemm64<<<dim3(NG / 128, 1, 1), 128>>>(
            sl1(p_agg, p_hw, 64), 64, gw2, gw2, 64, 64, 64,
            nullptr, nullptr, 0, 0, p_dinv, p_agg2, gb1, nullptr);
        edge_kernel<<<EE / 4, 256>>>(e_src, e_dst, p_hw, p_dinv, p_agg2);

        // diff_x = rbf @ (agg2 + gb2)  (B-loader bias fused; split-K 4) -> yB
        gemm64<<<dim3(NV / 128, 4, 1), 128>>>(
            sl1(p_rbf, yB, 64), NG, p_agg2, p_agg2, 64, NG, NG / 4,
            nullptr, nullptr, 0, 0, nullptr, nullptr, nullptr, gb2);
    }

    // final: out = y[0] @ last_w + last_b
    out_kernel<<<(NV * 8) / 256, 256>>>(p_y, last_w, last_b, out);
}

// round 7
// speedup vs baseline: 2.2006x; 1.0627x over previous
#include <cuda_runtime.h>
#include <math.h>
#include <stdint.h>

#define NV 4096
#define NG 2048
#define DD 64
#define KK 128
#define NBLK 4
#define EE 32768

// ---------------- scratch (device globals; no allocation allowed) ----------------
__device__ float g_rbf [NV * NG];        // [NV, NG]
__device__ float g_rbfT[NG * NV];        // [NG, NV]
__device__ float g_f   [NV * 128];       // [NV, 128] = [x | x_diff]
__device__ float g_y   [2 * NV * 64];    // double-buffered diff_x
__device__ float g_cat [NV * 128];       // [gX | gY]
__device__ float g_b2  [2 * NV * 64];    // [b_re ; b_im]
__device__ float g_mx  [NV * 64];        // mass * x
__device__ float g_xs  [KK * 64];
__device__ float g_W   [NBLK * 2 * KK * 64];  // per-block [Wre ; Wim]
__device__ float g_GE  [2 * NV * 128];   // [gradX@evecs ; gradY@evecs]
__device__ float g_eT  [KK * NV];        // evecs^T
__device__ float g_gx  [NG * 64];
__device__ float g_hw  [NG * 64];
__device__ float g_agg [NG * 64];
__device__ float g_agg2[NG * 64];
__device__ float g_deg [NG];
__device__ float g_dinv[NG];
__device__ int   g_rowptr[NG + 1];
__device__ int   g_cursor[NG];
__device__ int   g_srcs[EE];

// ---------------- tf32 helpers ----------------
__device__ __forceinline__ float tf32r(float x) {
    uint32_t r;
    asm("cvt.rna.tf32.f32 %0, %1;" : "=r"(r) : "f"(x));
    return __uint_as_float(r);
}
__device__ __forceinline__ void mma_tf32(float* c, const uint32_t* a, const uint32_t* b) {
    asm volatile(
        "mma.sync.aligned.m16n8k8.row.col.f32.tf32.tf32.f32 "
        "{%0,%1,%2,%3}, {%4,%5,%6,%7}, {%8,%9}, {%0,%1,%2,%3};"
        : "+f"(c[0]), "+f"(c[1]), "+f"(c[2]), "+f"(c[3])
        : "r"(a[0]), "r"(a[1]), "r"(a[2]), "r"(a[3]), "r"(b[0]), "r"(b[1]));
}

// per-z slice descriptors
struct Sl {
    const float* A[4];
    float*       C[4];
    int          ldc[4];
};

// ---------------- generic N=64 GEMM (tf32 MMA), BM=128, 128 threads -----------
// Register-prefetch double-buffered; one __syncthreads per k-tile.
// abias:  A-load  a = relu(a + abias[k])                       (GCN2 input fusion)
// bbias:  B-load  b = b + bbias[n]                             (agg2 + gb2 fusion)
// bexp_*: B-load  b = b * exp(-bexp_ev[k] * max(bexp_t[n],eps)) (spectral coef fusion)
// gridDim.y > 1 => split-K atomicAdd (caller zero-inits C).
__global__ __launch_bounds__(128) void gemm64(
    Sl sl, int lda,
    const float* __restrict__ B0, const float* __restrict__ B1, int ldb,
    int KB, int kchunk,
    const float* __restrict__ bias,
    const float* __restrict__ resid, int ldr, int act,
    const float* __restrict__ abias, const float* __restrict__ bbias,
    const float* __restrict__ bexp_ev, const float* __restrict__ bexp_t)
{
    __shared__ float As[2][128][36];
    __shared__ float Bs[2][32][72];

    const int z = blockIdx.z;
    const float* A = sl.A[z];
    const float* B = (z & 1) ? B1 : B0;
    float* C = sl.C[z];
    const int ldc = sl.ldc[z];

    const int tid    = threadIdx.x;
    const int warp   = tid >> 5;
    const int lane   = tid & 31;
    const int g      = lane >> 2;
    const int tg     = lane & 3;
    const int m0     = blockIdx.x * 128;
    const int warp_m = warp * 32;
    const int kbeg   = blockIdx.y * kchunk;
    const int ntile  = kchunk >> 5;

    const int am = tid >> 3;
    const int ak = (tid & 7) * 4;
    const int bk = tid >> 4;
    const int bn = (tid & 15) * 4;

    float4 bb = make_float4(0.f, 0.f, 0.f, 0.f);
    if (bbias) bb = *(const float4*)(bbias + bn);
    float4 tc = make_float4(0.f, 0.f, 0.f, 0.f);
    if (bexp_t) {
        tc = *(const float4*)(bexp_t + bn);
        tc.x = fmaxf(tc.x, 1e-8f); tc.y = fmaxf(tc.y, 1e-8f);
        tc.z = fmaxf(tc.z, 1e-8f); tc.w = fmaxf(tc.w, 1e-8f);
    }

    float4 rA[8], rB[4];
    float c[2][8][4];
#pragma unroll
    for (int mi = 0; mi < 2; mi++)
#pragma unroll
        for (int ni = 0; ni < 8; ni++)
#pragma unroll
            for (int r = 0; r < 4; r++) c[mi][ni][r] = 0.0f;

    {   // prologue tile 0
        const float* ap = A + (size_t)(m0 + am) * lda + kbeg + ak;
        const float* bp = B + (size_t)(kbeg + bk) * ldb + bn;
#pragma unroll
        for (int i = 0; i < 8; i++) rA[i] = *(const float4*)(ap + (size_t)(i * 16) * lda);
#pragma unroll
        for (int i = 0; i < 4; i++) rB[i] = *(const float4*)(bp + (size_t)(i * 8) * ldb);
    }

    int buf = 0;
    for (int it = 0; it < ntile; it++) {
        const int kst = kbeg + it * 32;
#pragma unroll
        for (int i = 0; i < 8; i++) {
            float4 v = rA[i];
            if (abias) {
                float4 ab = *(const float4*)(abias + kst + ak);
                v.x = fmaxf(v.x + ab.x, 0.f); v.y = fmaxf(v.y + ab.y, 0.f);
                v.z = fmaxf(v.z + ab.z, 0.f); v.w = fmaxf(v.w + ab.w, 0.f);
            }
            v.x = tf32r(v.x); v.y = tf32r(v.y); v.z = tf32r(v.z); v.w = tf32r(v.w);
            *(float4*)&As[buf][am + i * 16][ak] = v;
        }
#pragma unroll
        for (int i = 0; i < 4; i++) {
            float4 v = rB[i];
            if (bexp_ev) {
                float ev = bexp_ev[kst + bk + i * 8];
                v.x *= __expf(-ev * tc.x); v.y *= __expf(-ev * tc.y);
                v.z *= __expf(-ev * tc.z); v.w *= __expf(-ev * tc.w);
            }
            v.x += bb.x; v.y += bb.y; v.z += bb.z; v.w += bb.w;
            v.x = tf32r(v.x); v.y = tf32r(v.y); v.z = tf32r(v.z); v.w = tf32r(v.w);
            *(float4*)&Bs[buf][bk + i * 8][bn] = v;
        }
        __syncthreads();

        if (it + 1 < ntile) {
            int kb = kbeg + (it + 1) * 32;
            const float* ap = A + (size_t)(m0 + am) * lda + kb + ak;
            const float* bp = B + (size_t)(kb + bk) * ldb + bn;
#pragma unroll
            for (int i = 0; i < 8; i++) rA[i] = *(const float4*)(ap + (size_t)(i * 16) * lda);
#pragma unroll
            for (int i = 0; i < 4; i++) rB[i] = *(const float4*)(bp + (size_t)(i * 8) * ldb);
        }

#pragma unroll
        for (int k8 = 0; k8 < 32; k8 += 8) {
            uint32_t a[2][4];
#pragma unroll
            for (int mi = 0; mi < 2; mi++) {
                int r0 = warp_m + mi * 16 + g;
                a[mi][0] = __float_as_uint(As[buf][r0][k8 + tg]);
                a[mi][1] = __float_as_uint(As[buf][r0 + 8][k8 + tg]);
                a[mi][2] = __float_as_uint(As[buf][r0][k8 + tg + 4]);
                a[mi][3] = __float_as_uint(As[buf][r0 + 8][k8 + tg + 4]);
            }
            uint32_t b[8][2];
#pragma unroll
            for (int ni = 0; ni < 8; ni++) {
                b[ni][0] = __float_as_uint(Bs[buf][k8 + tg][ni * 8 + g]);
                b[ni][1] = __float_as_uint(Bs[buf][k8 + tg + 4][ni * 8 + g]);
            }
#pragma unroll
            for (int mi = 0; mi < 2; mi++)
#pragma unroll
                for (int ni = 0; ni < 8; ni++)
                    mma_tf32(c[mi][ni], a[mi], b[ni]);
        }
        buf ^= 1;
    }

    const bool split = (gridDim.y > 1);
#pragma unroll
    for (int mi = 0; mi < 2; mi++) {
#pragma unroll
        for (int rr = 0; rr < 2; rr++) {
            int m = m0 + warp_m + mi * 16 + g + rr * 8;
#pragma unroll
            for (int ni = 0; ni < 8; ni++) {
                int n = ni * 8 + tg * 2;
                float v0 = c[mi][ni][rr * 2 + 0];
                float v1 = c[mi][ni][rr * 2 + 1];
                if (split) {
                    atomicAdd(&C[(size_t)m * ldc + n],     v0);
                    atomicAdd(&C[(size_t)m * ldc + n + 1], v1);
                } else {
                    if (bias)  { v0 += bias[n]; v1 += bias[n + 1]; }
                    if (resid) { v0 += resid[(size_t)m * ldr + n];
                                 v1 += resid[(size_t)m * ldr + n + 1]; }
                    if (act)   { v0 = fmaxf(v0, 0.0f); v1 = fmaxf(v1, 0.0f); }
                    *(float2*)&C[(size_t)m * ldc + n] = make_float2(v0, v1);
                }
            }
        }
    }
}

// ---------------- fused 3-layer MLP (one launch) -------------------------------
// Phase-1 A-loader computes gfeat (cols 128:192) on the fly from cat/b2.
__device__ __forceinline__ float4 load_f_ext(
    const float* __restrict__ f, const float* __restrict__ cat,
    const float* __restrict__ b2, int m, int k)
{
    if (k < 128) return *(const float4*)(f + (size_t)m * 128 + k);
    int kk = k - 128;
    float4 gx = *(const float4*)(cat + (size_t)m * 128 + kk);
    float4 gy = *(const float4*)(cat + (size_t)m * 128 + 64 + kk);
    float4 br = *(const float4*)(b2 + (size_t)m * 64 + kk);
    float4 bi = *(const float4*)(b2 + (size_t)(NV * 64) + (size_t)m * 64 + kk);
    float4 r;
    r.x = tanhf(gx.x * br.x + gy.x * bi.x);
    r.y = tanhf(gx.y * br.y + gy.y * bi.y);
    r.z = tanhf(gx.z * br.z + gy.z * bi.z);
    r.w = tanhf(gx.w * br.w + gy.w * bi.w);
    return r;
}

__global__ __launch_bounds__(128) void mlp_kernel(
    float* __restrict__ f,                         // [NV,128]; writes cols 0:64
    const float* __restrict__ cat, const float* __restrict__ b2v,
    const float* __restrict__ w0, const float* __restrict__ b0,
    const float* __restrict__ w1, const float* __restrict__ b1,
    const float* __restrict__ w2, const float* __restrict__ b2)
{
    __shared__ float As[2][128][36];
    __shared__ float Bs[2][32][72];

    const int tid = threadIdx.x, warp = tid >> 5, lane = tid & 31;
    const int g = lane >> 2, tg = lane & 3;
    const int m0 = blockIdx.x * 128, warp_m = warp * 32;
    const int am = tid >> 3, ak = (tid & 7) * 4;
    const int bk = tid >> 4, bn = (tid & 15) * 4;

    float c[2][8][4];
#pragma unroll
    for (int mi = 0; mi < 2; mi++)
#pragma unroll
        for (int ni = 0; ni < 8; ni++)
#pragma unroll
            for (int r = 0; r < 4; r++) c[mi][ni][r] = 0.0f;

    // ---- phase 1: h1 = relu(fext @ w0 + b0), K=192 streamed (6 tiles) ----
    float4 rA[8], rB[4];
    {
#pragma unroll
        for (int i = 0; i < 8; i++)
            rA[i] = load_f_ext(f, cat, b2v, m0 + am + i * 16, ak);
        const float* bp = w0 + (size_t)bk * 64 + bn;
#pragma unroll
        for (int i = 0; i < 4; i++) rB[i] = *(const float4*)(bp + (size_t)(i * 8) * 64);
    }
    int buf = 0;
    for (int it = 0; it < 6; it++) {
#pragma unroll
        for (int i = 0; i < 8; i++) {
            float4 v = rA[i];
            v.x = tf32r(v.x); v.y = tf32r(v.y); v.z = tf32r(v.z); v.w = tf32r(v.w);
            *(float4*)&As[buf][am + i * 16][ak] = v;
        }
#pragma unroll
        for (int i = 0; i < 4; i++) {
            float4 v = rB[i];
            v.x = tf32r(v.x); v.y = tf32r(v.y); v.z = tf32r(v.z); v.w = tf32r(v.w);
            *(float4*)&Bs[buf][bk + i * 8][bn] = v;
        }
        __syncthreads();
        if (it + 1 < 6) {
            int kb = (it + 1) * 32;
#pragma unroll
            for (int i = 0; i < 8; i++)
                rA[i] = load_f_ext(f, cat, b2v, m0 + am + i * 16, kb + ak);
            const float* bp = w0 + (size_t)(kb + bk) * 64 + bn;
#pragma unroll
            for (int i = 0; i < 4; i++) rB[i] = *(const float4*)(bp + (size_t)(i * 8) * 64);
        }
#pragma unroll
        for (int k8 = 0; k8 < 32; k8 += 8) {
            uint32_t a[2][4];
#pragma unroll
            for (int mi = 0; mi < 2; mi++) {
                int r0 = warp_m + mi * 16 + g;
                a[mi][0] = __float_as_uint(As[buf][r0][k8 + tg]);
                a[mi][1] = __float_as_uint(As[buf][r0 + 8][k8 + tg]);
                a[mi][2] = __float_as_uint(As[buf][r0][k8 + tg + 4]);
                a[mi][3] = __float_as_uint(As[buf][r0 + 8][k8 + tg + 4]);
            }
            uint32_t b[8][2];
#pragma unroll
            for (int ni = 0; ni < 8; ni++) {
                b[ni][0] = __float_as_uint(Bs[buf][k8 + tg][ni * 8 + g]);
                b[ni][1] = __float_as_uint(Bs[buf][k8 + tg + 4][ni * 8 + g]);
            }
#pragma unroll
            for (int mi = 0; mi < 2; mi++)
#pragma unroll
                for (int ni = 0; ni < 8; ni++)
                    mma_tf32(c[mi][ni], a[mi], b[ni]);
        }
        buf ^= 1;
    }
    // h1 -> As (own-warp rows)
#pragma unroll
    for (int mi = 0; mi < 2; mi++)
#pragma unroll
        for (int rr = 0; rr < 2; rr++) {
            int ml = warp_m + mi * 16 + g + rr * 8;
#pragma unroll
            for (int ni = 0; ni < 8; ni++) {
                int n = ni * 8 + tg * 2;
                float v0 = fmaxf(c[mi][ni][rr * 2 + 0] + b0[n], 0.f);
                float v1 = fmaxf(c[mi][ni][rr * 2 + 1] + b0[n + 1], 0.f);
                *(float2*)&As[n >> 5][ml][n & 31] = make_float2(tf32r(v0), tf32r(v1));
            }
        }
    __syncthreads();

    // ---- phase 2: h2 = relu(h1 @ w1 + b1) ----
#pragma unroll
    for (int t = 0; t < 2; t++)
#pragma unroll
        for (int i = 0; i < 4; i++) {
            float4 v = *(const float4*)(w1 + (size_t)(t * 32 + bk + i * 8) * 64 + bn);
            v.x = tf32r(v.x); v.y = tf32r(v.y); v.z = tf32r(v.z); v.w = tf32r(v.w);
            *(float4*)&Bs[t][bk + i * 8][bn] = v;
        }
    __syncthreads();
#pragma unroll
    for (int mi = 0; mi < 2; mi++)
#pragma unroll
        for (int ni = 0; ni < 8; ni++)
#pragma unroll
            for (int r = 0; r < 4; r++) c[mi][ni][r] = 0.0f;
#pragma unroll
    for (int kt = 0; kt < 2; kt++)
#pragma unroll
        for (int k8 = 0; k8 < 32; k8 += 8) {
            uint32_t a[2][4];
#pragma unroll
            for (int mi = 0; mi < 2; mi++) {
                int r0 = warp_m + mi * 16 + g;
                a[mi][0] = __float_as_uint(As[kt][r0][k8 + tg]);
                a[mi][1] = __float_as_uint(As[kt][r0 + 8][k8 + tg]);
                a[mi][2] = __float_as_uint(As[kt][r0][k8 + tg + 4]);
                a[mi][3] = __float_as_uint(As[kt][r0 + 8][k8 + tg + 4]);
            }
            uint32_t b[8][2];
#pragma unroll
            for (int ni = 0; ni < 8; ni++) {
                b[ni][0] = __float_as_uint(Bs[kt][k8 + tg][ni * 8 + g]);
                b[ni][1] = __float_as_uint(Bs[kt][k8 + tg + 4][ni * 8 + g]);
            }
#pragma unroll
            for (int mi = 0; mi < 2; mi++)
#pragma unroll
                for (int ni = 0; ni < 8; ni++)
                    mma_tf32(c[mi][ni], a[mi], b[ni]);
        }
#pragma unroll
    for (int mi = 0; mi < 2; mi++)
#pragma unroll
        for (int rr = 0; rr < 2; rr++) {
            int ml = warp_m + mi * 16 + g + rr * 8;
#pragma unroll
            for (int ni = 0; ni < 8; ni++) {
                int n = ni * 8 + tg * 2;
                float v0 = fmaxf(c[mi][ni][rr * 2 + 0] + b1[n], 0.f);
                float v1 = fmaxf(c[mi][ni][rr * 2 + 1] + b1[n + 1], 0.f);
                *(float2*)&As[n >> 5][ml][n & 31] = make_float2(tf32r(v0), tf32r(v1));
            }
        }
    __syncthreads();

    // ---- phase 3: x' = h2 @ w2 + b2 + x ----
#pragma unroll
    for (int t = 0; t < 2; t++)
#pragma unroll
        for (int i = 0; i < 4; i++) {
            float4 v = *(const float4*)(w2 + (size_t)(t * 32 + bk + i * 8) * 64 + bn);
            v.x = tf32r(v.x); v.y = tf32r(v.y); v.z = tf32r(v.z); v.w = tf32r(v.w);
            *(float4*)&Bs[t][bk + i * 8][bn] = v;
        }
    __syncthreads();
#pragma unroll
    for (int mi = 0; mi < 2; mi++)
#pragma unroll
        for (int ni = 0; ni < 8; ni++)
#pragma unroll
            for (int r = 0; r < 4; r++) c[mi][ni][r] = 0.0f;
#pragma unroll
    for (int kt = 0; kt < 2; kt++)
#pragma unroll
        for (int k8 = 0; k8 < 32; k8 += 8) {
            uint32_t a[2][4];
#pragma unroll
            for (int mi = 0; mi < 2; mi++) {
                int r0 = warp_m + mi * 16 + g;
                a[mi][0] = __float_as_uint(As[kt][r0][k8 + tg]);
                a[mi][1] = __float_as_uint(As[kt][r0 + 8][k8 + tg]);
                a[mi][2] = __float_as_uint(As[kt][r0][k8 + tg + 4]);
                a[mi][3] = __float_as_uint(As[kt][r0 + 8][k8 + tg + 4]);
            }
            uint32_t b[8][2];
#pragma unroll
            for (int ni = 0; ni < 8; ni++) {
                b[ni][0] = __float_as_uint(Bs[kt][k8 + tg][ni * 8 + g]);
                b[ni][1] = __float_as_uint(Bs[kt][k8 + tg + 4][ni * 8 + g]);
            }
#pragma unroll
            for (int mi = 0; mi < 2; mi++)
#pragma unroll
                for (int ni = 0; ni < 8; ni++)
                    mma_tf32(c[mi][ni], a[mi], b[ni]);
        }
#pragma unroll
    for (int mi = 0; mi < 2; mi++)
#pragma unroll
        for (int rr = 0; rr < 2; rr++) {
            int m = m0 + warp_m + mi * 16 + g + rr * 8;
#pragma unroll
            for (int ni = 0; ni < 8; ni++) {
                int n = ni * 8 + tg * 2;
                float v0 = c[mi][ni][rr * 2 + 0] + b2[n]     + f[(size_t)m * 128 + n];
                float v1 = c[mi][ni][rr * 2 + 1] + b2[n + 1] + f[(size_t)m * 128 + n + 1];
                *(float2*)&f[(size_t)m * 128 + n] = make_float2(v0, v1);
            }
        }
}

// ---------------- rbf coupling + transpose (fast math) ----------------
__device__ __forceinline__ float exp_neg_04(float dist) {
    float t  = dist * -0.5770780163555852f;
    float fn = floorf(t);
    float fr = t - fn;
    float p  = 1.5403530e-4f;
    p = fmaf(p, fr, 1.33335581e-3f);
    p = fmaf(p, fr, 9.61812911e-3f);
    p = fmaf(p, fr, 5.55041087e-2f);
    p = fmaf(p, fr, 2.40226507e-1f);
    p = fmaf(p, fr, 6.93147181e-1f);
    p = fmaf(p, fr, 1.0f);
    int n = (int)fn;
    n = n < -126 ? -126 : n;
    return p * __int_as_float((n + 127) << 23);
}

__global__ void rbf_kernel(const float* __restrict__ vert, const float* __restrict__ gp,
                           float* __restrict__ rbf, float* __restrict__ rbfT)
{
    __shared__ float tile[32][33];
    int tx = threadIdx.x, ty = threadIdx.y;
    int g = blockIdx.x * 32 + tx;
    int v = blockIdx.y * 32 + ty;
    float vx = vert[v * 3], vy = vert[v * 3 + 1], vz = vert[v * 3 + 2];
    float gx = gp[g * 3],  gy = gp[g * 3 + 1],  gz = gp[g * 3 + 2];
    float dx = vx - gx, dy = vy - gy, dz = vz - gz;
    float d2 = fmaf(dx, dx, fmaf(dy, dy, dz * dz));
    d2 = fmaxf(d2, 1e-24f);
    float rs;
    asm("rsqrt.approx.f32 %0, %1;" : "=f"(rs) : "f"(d2));
    float r = exp_neg_04(d2 * rs);
    rbf[(size_t)v * NG + g] = r;
    tile[ty][tx] = r;
    __syncthreads();
    int g2 = blockIdx.x * 32 + ty;
    int v2 = blockIdx.y * 32 + tx;
    rbfT[(size_t)g2 * NV + v2] = tile[tx][ty];
}

// ---------------- transpose evecs ----------------
__global__ void transpose_kernel(const float* __restrict__ in, float* __restrict__ out)
{
    __shared__ float t[32][33];
    int x = blockIdx.x * 32 + threadIdx.x;
    int y = blockIdx.y * 32 + threadIdx.y;
    t[threadIdx.y][threadIdx.x] = in[(size_t)y * 128 + x];
    __syncthreads();
    int ox = blockIdx.y * 32 + threadIdx.x;
    int oy = blockIdx.x * 32 + threadIdx.y;
    out[(size_t)oy * NV + ox] = t[threadIdx.x][threadIdx.y];
}

// ---------------- elementwise (with fused zeroing) ----------------
__global__ void massx_kernel(const float* __restrict__ y, const float* __restrict__ mass,
                             float* __restrict__ f, float* __restrict__ mx,
                             float* __restrict__ yB, float* __restrict__ xs,
                             float* __restrict__ gx)
{
    int gid = blockIdx.x * 256 + threadIdx.x;   // NV*64
    int v = gid >> 6, d = gid & 63;
    float x = y[gid];
    f[v * 128 + d] = x;
    mx[gid] = mass[v] * x;
    yB[gid] = 0.0f;
    if (gid < KK * 64) xs[gid] = 0.0f;
    if (gid < NG * 64) gx[gid] = 0.0f;
}

__global__ void wcat_kernel(const float* __restrict__ are, const float* __restrict__ aim,
                            float* __restrict__ W)
{
    int gid = blockIdx.x * 256 + threadIdx.x;   // NBLK*KK*64
    int blk = gid >> 13;
    int r = gid & 8191;
    int k = r >> 6, d = r & 63;
    const float* a_re = are + blk * 64 * 64;
    const float* a_im = aim + blk * 64 * 64;
    float wre, wim;
    if (k < 64) { wre = a_re[k * 64 + d];         wim = a_im[k * 64 + d]; }
    else        { wre = -a_im[(k - 64) * 64 + d]; wim = a_re[(k - 64) * 64 + d]; }
    float* Wb = W + blk * 2 * KK * 64;
    Wb[r]            = wre;
    Wb[KK * 64 + r]  = wim;
}

// ---------------- GCN graph setup: CSR build ----------------
__global__ void deg_kernel(const int* __restrict__ dst, float* __restrict__ deg)
{
    int e = blockIdx.x * 256 + threadIdx.x;
    atomicAdd(&deg[dst[e]], 1.0f);
}
__global__ void dinv_kernel(const float* __restrict__ deg, float* __restrict__ dinv)
{
    int i = blockIdx.x * 256 + threadIdx.x;
    dinv[i] = rsqrtf(deg[i] + 1.0f);
}
// single-block scan of 2048 degrees -> exclusive rowptr; zero cursors
__global__ __launch_bounds__(1024) void scan_kernel(const float* __restrict__ deg,
                                                    int* __restrict__ rowptr,
                                                    int* __restrict__ cursor)
{
    __shared__ int p[1024];
    int t = threadIdx.x;
    int d0 = (int)deg[2 * t], d1 = (int)deg[2 * t + 1];
    p[t] = d0 + d1;
    __syncthreads();
    for (int off = 1; off < 1024; off <<= 1) {
        int v = p[t];
        if (t >= off) v += p[t - off];
        __syncthreads();
        p[t] = v;
        __syncthreads();
    }
    int excl = (t == 0) ? 0 : p[t - 1];
    rowptr[2 * t]     = excl;
    rowptr[2 * t + 1] = excl + d0;
    if (t == 1023) rowptr[2048] = p[1023];
    cursor[2 * t] = 0;
    cursor[2 * t + 1] = 0;
}
__global__ void scatter_kernel(const int* __restrict__ src, const int* __restrict__ dst,
                               const int* __restrict__ rowptr, int* __restrict__ cursor,
                               int* __restrict__ srcs)
{
    int e = blockIdx.x * 256 + threadIdx.x;
    int s = src[e], t = dst[e];
    int pos = rowptr[t] + atomicAdd(&cursor[t], 1);
    srcs[pos] = s;
}
// pull-based aggregation: agg[i,d] = dinv[i]*(dinv[i]*hw[i,d] + sum_e dinv[s]*hw[s,d])
__global__ void csr_agg_kernel(const float* __restrict__ hw, const float* __restrict__ dinv,
                               const int* __restrict__ rowptr, const int* __restrict__ srcs,
                               float* __restrict__ agg)
{
    int gid = blockIdx.x * 256 + threadIdx.x;   // NG*64
    int i = gid >> 6, d = gid & 63;
    float di = dinv[i];
    float acc = hw[i * 64 + d] * di;
    int r1 = rowptr[i + 1];
    for (int r = rowptr[i]; r < r1; r++) {
        int s = srcs[r];
        acc += hw[s * 64 + d] * dinv[s];
    }
    agg[gid] = acc * di;
}

// ---------------- head / tail ----------------
__global__ void lin1_kernel(const float* __restrict__ sx, const float* __restrict__ w,
                            const float* __restrict__ b, float* __restrict__ y)
{
    int gid = blockIdx.x * 256 + threadIdx.x;   // NV*64
    int v = gid >> 6, d = gid & 63;
    float acc = b[d];
#pragma unroll
    for (int j = 0; j < 5; j++) acc += sx[v * 5 + j] * w[j * 64 + d];
    y[gid] = acc;
}

__global__ void out_kernel(const float* __restrict__ y, const float* __restrict__ w,
                           const float* __restrict__ b, float* __restrict__ out)
{
    int gid = blockIdx.x * 256 + threadIdx.x;   // NV*8
    int v = gid >> 3, c = gid & 7;
    float acc = b[c];
#pragma unroll 8
    for (int d = 0; d < 64; d++) acc += y[v * 64 + d] * w[d * 8 + c];
    out[gid] = acc;
}

// ---------------- host ----------------
static inline Sl sl1(const float* A, float* C, int ldc) {
    Sl s; for (int i = 0; i < 4; i++) { s.A[i] = A; s.C[i] = C; s.ldc[i] = ldc; }
    return s;
}

extern "C" void kernel_launch(void* const* d_in, const int* in_sizes, int n_in,
                              void* d_out, int out_size)
{
    static bool inited = false;
    static float *p_rbf, *p_rbfT, *p_f, *p_y, *p_cat, *p_b2, *p_mx,
                 *p_xs, *p_W, *p_GE, *p_eT, *p_gx, *p_hw, *p_agg, *p_agg2,
                 *p_deg, *p_dinv;
    static int *p_rowptr, *p_cursor, *p_srcs;
    if (!inited) {
        cudaGetSymbolAddress((void**)&p_rbf,  g_rbf);
        cudaGetSymbolAddress((void**)&p_rbfT, g_rbfT);
        cudaGetSymbolAddress((void**)&p_f,    g_f);
        cudaGetSymbolAddress((void**)&p_y,    g_y);
        cudaGetSymbolAddress((void**)&p_cat,  g_cat);
        cudaGetSymbolAddress((void**)&p_b2,   g_b2);
        cudaGetSymbolAddress((void**)&p_mx,   g_mx);
        cudaGetSymbolAddress((void**)&p_xs,   g_xs);
        cudaGetSymbolAddress((void**)&p_W,    g_W);
        cudaGetSymbolAddress((void**)&p_GE,   g_GE);
        cudaGetSymbolAddress((void**)&p_eT,   g_eT);
        cudaGetSymbolAddress((void**)&p_gx,   g_gx);
        cudaGetSymbolAddress((void**)&p_hw,   g_hw);
        cudaGetSymbolAddress((void**)&p_agg,  g_agg);
        cudaGetSymbolAddress((void**)&p_agg2, g_agg2);
        cudaGetSymbolAddress((void**)&p_deg,  g_deg);
        cudaGetSymbolAddress((void**)&p_dinv, g_dinv);
        cudaGetSymbolAddress((void**)&p_rowptr, g_rowptr);
        cudaGetSymbolAddress((void**)&p_cursor, g_cursor);
        cudaGetSymbolAddress((void**)&p_srcs,   g_srcs);
        inited = true;
    }

    const float* surf_x    = (const float*)d_in[0];
    const float* mass      = (const float*)d_in[1];
    const float* evals     = (const float*)d_in[2];
    const float* evecs     = (const float*)d_in[3];
    const float* gradX     = (const float*)d_in[4];
    const float* gradY     = (const float*)d_in[5];
    const float* vertices  = (const float*)d_in[6];
    const float* graph_pos = (const float*)d_in[8];
    const float* lin1_w    = (const float*)d_in[9];
    const float* lin1_b    = (const float*)d_in[10];
    const float* last_w    = (const float*)d_in[13];
    const float* last_b    = (const float*)d_in[14];
    const float* diff_time = (const float*)d_in[15];
    const float* A_re      = (const float*)d_in[16];
    const float* A_im      = (const float*)d_in[17];
    const float* mlp_w0    = (const float*)d_in[18];
    const float* mlp_b0    = (const float*)d_in[19];
    const float* mlp_w1    = (const float*)d_in[20];
    const float* mlp_b1    = (const float*)d_in[21];
    const float* mlp_w2    = (const float*)d_in[22];
    const float* mlp_b2    = (const float*)d_in[23];
    const float* gcn_w1    = (const float*)d_in[24];
    const float* gcn_b1    = (const float*)d_in[25];
    const float* gcn_w2    = (const float*)d_in[26];
    const float* gcn_b2    = (const float*)d_in[27];
    const int*   eidx      = (const int*)d_in[28];
    const int*   e_src     = eidx;
    const int*   e_dst     = eidx + EE;
    float* out = (float*)d_out;

    // ---- setup ----
    rbf_kernel<<<dim3(NG / 32, NV / 32), dim3(32, 32)>>>(vertices, graph_pos, p_rbf, p_rbfT);

    cudaMemsetAsync(p_deg, 0, NG * sizeof(float));
    deg_kernel<<<EE / 256, 256>>>(e_dst, p_deg);
    dinv_kernel<<<NG / 256, 256>>>(p_deg, p_dinv);
    scan_kernel<<<1, 1024>>>(p_deg, p_rowptr, p_cursor);
    scatter_kernel<<<EE / 256, 256>>>(e_src, e_dst, p_rowptr, p_cursor, p_srcs);

    transpose_kernel<<<dim3(KK / 32, NV / 32), dim3(32, 32)>>>(evecs, p_eT);
    lin1_kernel<<<NV * 64 / 256, 256>>>(surf_x, lin1_w, lin1_b, p_y);       // -> y[0]
    wcat_kernel<<<NBLK * KK * 64 / 256, 256>>>(A_re, A_im, p_W);            // all blocks

    // GE = [gradX@evecs(lo) ; gradX@evecs(hi) ; gradY@evecs(lo) ; gradY@evecs(hi)]
    {
        Sl s;
        s.A[0] = gradX; s.A[1] = gradX; s.A[2] = gradY; s.A[3] = gradY;
        s.C[0] = p_GE;            s.C[1] = p_GE + 64;
        s.C[2] = p_GE + NV * 128; s.C[3] = p_GE + NV * 128 + 64;
        s.ldc[0] = s.ldc[1] = s.ldc[2] = s.ldc[3] = 128;
        gemm64<<<dim3(NV / 128, 1, 4), 128>>>(
            s, NV, evecs, evecs + 64, 128, NV, NV,
            nullptr, nullptr, 0, 0, nullptr, nullptr, nullptr, nullptr);
    }

    for (int blk = 0; blk < NBLK; blk++) {
        const float* t   = diff_time + blk * 64;
        const float* w0  = mlp_w0 + blk * 192 * 64;
        const float* b0  = mlp_b0 + blk * 64;
        const float* w1  = mlp_w1 + blk * 64 * 64;
        const float* b1  = mlp_b1 + blk * 64;
        const float* w2  = mlp_w2 + blk * 64 * 64;
        const float* b2m = mlp_b2 + blk * 64;
        const float* gw1 = gcn_w1 + blk * 64 * 64;
        const float* gb1 = gcn_b1 + blk * 64;
        const float* gw2 = gcn_w2 + blk * 64 * 64;
        const float* gb2 = gcn_b2 + blk * 64;
        const float* Wb  = p_W + blk * 2 * KK * 64;
        float* yA = p_y + (blk & 1) * NV * 64;        // read
        float* yB = p_y + (1 - (blk & 1)) * NV * 64;  // write

        // x -> f[:,0:64], mx = mass*x ; zero yB + xs + gx
        massx_kernel<<<NV * 64 / 256, 256>>>(yA, mass, p_f, p_mx, yB, p_xs, p_gx);

        // xs = evecsT @ mx  (split-K 16)
        gemm64<<<dim3(1, 16, 1), 128>>>(
            sl1(p_eT, p_xs, 64), NV, p_mx, p_mx, 64, NV, NV / 16,
            nullptr, nullptr, 0, 0, nullptr, nullptr, nullptr, nullptr);

        // [x_diff ; gX ; gY] = [evecs ; GE_X ; GE_Y] @ (coef * xs)  (exp fused in B-loader)
        {
            Sl s;
            s.A[0] = evecs;          s.C[0] = p_f + 64;   s.ldc[0] = 128;
            s.A[1] = p_GE;           s.C[1] = p_cat;      s.ldc[1] = 128;
            s.A[2] = p_GE + NV*128;  s.C[2] = p_cat + 64; s.ldc[2] = 128;
            s.A[3] = evecs;          s.C[3] = p_f + 64;   s.ldc[3] = 128;
            gemm64<<<dim3(NV / 128, 1, 3), 128>>>(
                s, 128, p_xs, p_xs, 64, KK, KK,
                nullptr, nullptr, 0, 0, nullptr, nullptr, evals, t);
        }

        // b_re|b_im = cat @ [Wre|Wim]
        {
            Sl s;
            s.A[0] = p_cat; s.C[0] = p_b2;           s.ldc[0] = 64;
            s.A[1] = p_cat; s.C[1] = p_b2 + NV * 64; s.ldc[1] = 64;
            s.A[2] = p_cat; s.C[2] = p_b2;           s.ldc[2] = 64;
            s.A[3] = p_cat; s.C[3] = p_b2;           s.ldc[3] = 64;
            gemm64<<<dim3(NV / 128, 1, 2), 128>>>(
                s, 128, Wb, Wb + KK * 64, 64, KK, KK,
                nullptr, nullptr, 0, 0, nullptr, nullptr, nullptr, nullptr);
        }

        // fused MLP (gfeat computed in-loader) + residual -> f[:,0:64]
        mlp_kernel<<<NV / 128, 128>>>(p_f, p_cat, p_b2, w0, b0, w1, b1, w2, b2m);

        // gx = rbf^T @ diff_x (split-K 8)
        gemm64<<<dim3(NG / 128, 8, 1), 128>>>(
            sl1(p_rbfT, p_gx, 64), NV, p_f, p_f, 128, NV, NV / 8,
            nullptr, nullptr, 0, 0, nullptr, nullptr, nullptr, nullptr);

        // GCN layer 1: hw = gx@W1 ; agg1 = CSR aggregation
        gemm64<<<dim3(NG / 128, 1, 1), 128>>>(
            sl1(p_gx, p_hw, 64), 64, gw1, gw1, 64, 64, 64,
            nullptr, nullptr, 0, 0, nullptr, nullptr, nullptr, nullptr);
        csr_agg_kernel<<<NG * 64 / 256, 256>>>(p_hw, p_dinv, p_rowptr, p_srcs, p_agg);

        // GCN layer 2: hw = relu(agg1+gb1)@W2 (A-loader fused) ; agg2 = CSR aggregation
        gemm64<<<dim3(NG / 128, 1, 1), 128>>>(
            sl1(p_agg, p_hw, 64), 64, gw2, gw2, 64, 64, 64,
            nullptr, nullptr, 0, 0, gb1, nullptr, nullptr, nullptr);
        csr_agg_kernel<<<NG * 64 / 256, 256>>>(p_hw, p_dinv, p_rowptr, p_srcs, p_agg2);

        // diff_x = rbf @ (agg2 + gb2)  (B-loader bias fused; split-K 4) -> yB
        gemm64<<<dim3(NV / 128, 4, 1), 128>>>(
            sl1(p_rbf, yB, 64), NG, p_agg2, p_agg2, 64, NG, NG / 4,
            nullptr, nullptr, 0, 0, nullptr, gb2, nullptr, nullptr);
    }

    // final: out = y[0] @ last_w + last_b
    out_kernel<<<(NV * 8) / 256, 256>>>(p_y, last_w, last_b, out);
}